// round 2
// baseline (speedup 1.0000x reference)
#include <cuda_runtime.h>
#include <math.h>

#define NN 50000
#define NE 800000
#define FIN 64
#define HH 128
#define LL 3
#define CC 4
#define KK 32
#define NOPS 7
#define NB 512
#define NOUT 10
#define BNG 120

// ------------------------- device scratch (no allocs) -------------------------
__device__ float g_gr[(LL+1)*NN*HH];   // gr[0..3]
__device__ float g_xw[NN*HH];          // x + vn[batch]
__device__ float g_sum[NN*HH];
__device__ float g_nrm[NN*HH];
__device__ float g_att[NN*HH];
__device__ float g_y[NN*HH];
__device__ float g_s0[NN];
__device__ float g_s1[NN];
__device__ float g_sinv[NN];
__device__ float g_dinv[NN];
__device__ float g_minv[NN];
__device__ float g_eedge[NE];
__device__ int   g_deg[NN];
__device__ int   g_rowptr[NN+1];
__device__ int   g_cursor[NN];
__device__ int   g_csrsrc[NE];
__device__ int   g_bstart[NB+1];
__device__ float g_wmix[LL*CC*NOPS];
__device__ float g_vn[NB*HH];
__device__ float g_vt[NB*HH];
__device__ float g_h1[NB*2*HH];
__device__ float g_h2[NB*HH];
__device__ float g_part[2*BNG*HH];
__device__ float g_scale[HH];
__device__ float g_shift[HH];
__device__ float g_pooled[NB*8*HH];

// ------------------------- f32x2 helpers -------------------------
__device__ __forceinline__ double pk2(float a){
  double d; asm("mov.b64 %0, {%1, %1};" : "=d"(d) : "f"(a)); return d;
}
__device__ __forceinline__ void fmaX2(double &d, double a, double b){
  asm("fma.rn.f32x2 %0, %1, %2, %0;" : "+d"(d) : "d"(a), "d"(b));
}
__device__ __forceinline__ void upk2(double d, float &lo, float &hi){
  asm("mov.b64 {%0, %1}, %2;" : "=f"(lo), "=f"(hi) : "d"(d));
}

// ------------------------- CSR build -------------------------
__global__ void k_zero_deg(){
  int i = blockIdx.x*blockDim.x + threadIdx.x;
  if (i < NN) g_deg[i] = 0;
}
__global__ void k_count(const int* __restrict__ dst){
  int e = blockIdx.x*blockDim.x + threadIdx.x;
  if (e < NE) atomicAdd(&g_deg[dst[e]], 1);
}
__global__ void k_scan(){
  __shared__ int sm[1024];
  const int CH = (NN + 1023)/1024;
  int t = threadIdx.x;
  int s = 0;
  for (int i=0;i<CH;i++){ int idx = t*CH+i; if (idx<NN) s += g_deg[idx]; }
  sm[t] = s; __syncthreads();
  for (int off=1; off<1024; off<<=1){
    int v = (t>=off) ? sm[t-off] : 0;
    __syncthreads();
    if (t>=off) sm[t] += v;
    __syncthreads();
  }
  int run = (t>0)? sm[t-1] : 0;
  for (int i=0;i<CH;i++){ int idx=t*CH+i; if (idx<NN){ g_rowptr[idx]=run; run += g_deg[idx]; } }
  if (t==1023) g_rowptr[NN] = sm[1023];
}
__global__ void k_nodeprep(){
  int i = blockIdx.x*blockDim.x + threadIdx.x;
  if (i < NN){
    g_cursor[i] = g_rowptr[i];
    float dc = (float)max(g_deg[i], 1);
    g_dinv[i] = rsqrtf(dc);
    g_minv[i] = 1.f/dc;
  }
}
__global__ void k_scatter(const int* __restrict__ src, const int* __restrict__ dst){
  int e = blockIdx.x*blockDim.x + threadIdx.x;
  if (e < NE){
    int slot = atomicAdd(&g_cursor[dst[e]], 1);
    g_csrsrc[slot] = src[e];
  }
}
__global__ void k_bstart(const int* __restrict__ batch){
  int i = blockIdx.x*blockDim.x + threadIdx.x;
  if (i >= NN) return;
  int b = batch[i];
  if (i == 0){ for (int bb=0; bb<=b; bb++) g_bstart[bb] = 0; }
  else { int p = batch[i-1]; for (int bb=p+1; bb<=b; bb++) g_bstart[bb] = i; }
  if (i == NN-1){ for (int bb=b+1; bb<=NB; bb++) g_bstart[bb] = NN; }
}
__global__ void k_prepw(const float* __restrict__ alphas){
  int g = threadIdx.x;
  if (g < LL*CC){
    const float* a = alphas + g*NOPS;
    float mx = a[0];
    for (int o=1;o<NOPS;o++) mx = fmaxf(mx, a[o]);
    float e[NOPS]; float s = 0.f;
    for (int o=0;o<NOPS;o++){ e[o] = expf(a[o]-mx); s += e[o]; }
    for (int o=0;o<NOPS;o++) g_wmix[g*NOPS+o] = e[o]/s;
  }
}
__global__ void k_vninit(const float* __restrict__ vn0){
  int i = blockIdx.x*blockDim.x + threadIdx.x;
  if (i < NB*HH) g_vn[i] = vn0[i & (HH-1)];
}

// ------------------------- lin1 + ELU -------------------------
__global__ void __launch_bounds__(128) k_lin1(const float* __restrict__ x,
    const float* __restrict__ W, const float* __restrict__ bias){
  __shared__ float Wt[HH*68];
  __shared__ float xs[16][FIN];
  int tid = threadIdx.x;
  for (int i=tid; i<FIN*HH; i+=128){ int h=i>>7, c=i&127; Wt[c*68+h] = W[i]; }
  int n0 = blockIdx.x*16;
  for (int i=tid; i<16*FIN; i+=128){
    int nl=i>>6, h=i&63; int n=n0+nl;
    xs[nl][h] = (n<NN)? x[n*FIN+h] : 0.f;
  }
  __syncthreads();
  float acc[16];
  float bv = bias[tid];
  #pragma unroll
  for (int nl=0;nl<16;nl++) acc[nl]=bv;
  #pragma unroll
  for (int h4=0; h4<FIN/4; h4++){
    float4 w4 = *(const float4*)&Wt[tid*68 + h4*4];
    #pragma unroll
    for (int nl=0;nl<16;nl++){
      float4 x4 = *(const float4*)&xs[nl][h4*4];
      acc[nl] += w4.x*x4.x + w4.y*x4.y + w4.z*x4.z + w4.w*x4.w;
    }
  }
  #pragma unroll
  for (int nl=0;nl<16;nl++){
    int n = n0+nl;
    if (n<NN){
      float a = acc[nl];
      a = a>0.f ? a : expm1f(a);
      g_gr[(size_t)n*HH+tid] = a;
    }
  }
}

// ------------------------- per-layer node prep -------------------------
__global__ void k_nodeA(const int* __restrict__ batch, const float* __restrict__ atta, int l){
  int w = (blockIdx.x*blockDim.x + threadIdx.x) >> 5;
  int lane = threadIdx.x & 31;
  if (w >= NN) return;
  int b = batch[w];
  float4 xv = ((const float4*)(g_gr + (size_t)l*NN*HH))[w*32 + lane];
  float4 vv = ((const float4*)g_vn)[b*32 + lane];
  xv.x += vv.x; xv.y += vv.y; xv.z += vv.z; xv.w += vv.w;
  ((float4*)g_xw)[w*32 + lane] = xv;
  float4 a0 = ((const float4*)(atta + l*2*HH))[lane];
  float4 a1 = ((const float4*)(atta + l*2*HH + HH))[lane];
  float s0 = xv.x*a0.x + xv.y*a0.y + xv.z*a0.z + xv.w*a0.w;
  float s1 = xv.x*a1.x + xv.y*a1.y + xv.z*a1.z + xv.w*a1.w;
  #pragma unroll
  for (int off=16; off; off>>=1){
    s0 += __shfl_xor_sync(0xffffffffu, s0, off);
    s1 += __shfl_xor_sync(0xffffffffu, s1, off);
  }
  if (lane==0){ g_s0[w]=s0; g_s1[w]=s1; }
}

// segment softmax scalars (per-dst max, exp, sum)
__global__ void k_att(){
  int n = blockIdx.x*blockDim.x + threadIdx.x;
  if (n >= NN) return;
  int s = g_rowptr[n], e = g_rowptr[n+1];
  float s1v = g_s1[n];
  float m = -1e30f;
  for (int j=s;j<e;j++){
    float ev = g_s0[g_csrsrc[j]] + s1v;
    ev = ev>0.f ? ev : 0.2f*ev;   // leaky_relu(0.2)
    g_eedge[j]=ev;
    m = fmaxf(m,ev);
  }
  if (e==s) m = 0.f;
  float ss=0.f;
  for (int j=s;j<e;j++){
    float p = expf(g_eedge[j]-m);
    g_eedge[j]=p;
    ss+=p;
  }
  g_sinv[n] = 1.f/(ss+1e-16f);
}

// fused gather: sum_nb, gcn-norm agg, attention agg in one edge pass
__global__ void k_gather(){
  int w = (blockIdx.x*blockDim.x + threadIdx.x) >> 5;
  int lane = threadIdx.x & 31;
  if (w >= NN) return;
  int s = g_rowptr[w], e = g_rowptr[w+1];
  float dv = g_dinv[w];
  float si = g_sinv[w];
  float4 a_s = make_float4(0.f,0.f,0.f,0.f);
  float4 a_n = a_s, a_a = a_s;
  for (int j=s; j<e; j++){
    int sn = g_csrsrc[j];
    float p  = g_eedge[j];
    float nw = g_dinv[sn]*dv;
    float ca = p*si;
    float4 xv = ((const float4*)g_xw)[sn*32 + lane];
    a_s.x+=xv.x;      a_s.y+=xv.y;      a_s.z+=xv.z;      a_s.w+=xv.w;
    a_n.x+=nw*xv.x;   a_n.y+=nw*xv.y;   a_n.z+=nw*xv.z;   a_n.w+=nw*xv.w;
    a_a.x+=ca*xv.x;   a_a.y+=ca*xv.y;   a_a.z+=ca*xv.z;   a_a.w+=ca*xv.w;
  }
  ((float4*)g_sum)[w*32+lane]=a_s;
  ((float4*)g_nrm)[w*32+lane]=a_n;
  ((float4*)g_att)[w*32+lane]=a_a;
}

// ------------------------- the big fused GEMM+LN+mix kernel -------------------------
// block: 64-node tile, 256 threads (tx 0..15 = 8 cols each, ty 0..15 = 4 nodes each)
// loops over 7 ops; builds agg tile in smem; fp32x2-packed GEMM; epilogue does
// bias + LayerNorm(K=32) + ln affine + DARTS mixing weight accumulation.
#define SMEM_MIX ((128*65 + 128*132 + 256)*4)
__global__ void __launch_bounds__(256,2) k_mix(int l,
    const float* __restrict__ Wops, const float* __restrict__ bops,
    const float* __restrict__ lng, const float* __restrict__ lnb){
  extern __shared__ float sm[];
  float* Ast = sm;                         // [128][65] transposed agg tile
  float* Ws  = sm + 128*65;                // [128][132]
  float* s_lg = sm + 128*65 + 128*132;     // [128]
  float* s_lb = s_lg + 128;
  int tid = threadIdx.x;
  int tx = tid & 15, ty = tid >> 4;
  int n0 = blockIdx.x * 64;
  if (tid < 128){ s_lg[tid] = lng[l*128+tid]; s_lb[tid] = lnb[l*128+tid]; }
  int c  = tx >> 2;
  int kb = (tx & 3) * 8;
  float mixv[4][8];
  #pragma unroll
  for (int i=0;i<4;i++)
    #pragma unroll
    for (int j=0;j<8;j++) mixv[i][j]=0.f;

  for (int o=0; o<NOPS; o++){
    __syncthreads();
    // build transposed agg tile
    #pragma unroll 1
    for (int it=0; it<32; it++){
      int lin = it*256 + tid;
      int nl = lin >> 7, h = lin & 127;
      int n = n0 + nl;
      float v = 0.f;
      if (n < NN){
        size_t idx = (size_t)n*HH + h;
        switch(o){
          case 0: case 5: v = g_nrm[idx]; break;
          case 1: v = g_xw[idx] + g_sum[idx]; break;
          case 2: v = g_att[idx]; break;
          case 3: v = g_xw[idx] + g_sum[idx]*g_minv[n]; break;
          case 4: v = g_sum[idx]*g_minv[n]; break;
          default: v = g_xw[idx]; break;
        }
      }
      Ast[h*65 + nl] = v;
    }
    // load W tile: Ws[h][c*32+k] = W_ops[l][c][o][h][k]
    #pragma unroll 1
    for (int c2=0; c2<CC; c2++){
      const float* wp = Wops + (((size_t)(l*CC + c2)*NOPS + o)*HH)*KK;
      #pragma unroll 1
      for (int it=0; it<16; it++){
        int lin = it*256 + tid;
        int h = lin >> 5, k = lin & 31;
        Ws[h*132 + c2*32 + k] = wp[lin];
      }
    }
    __syncthreads();
    double acc[16];
    #pragma unroll
    for (int i=0;i<16;i++) acc[i]=0.0;
    #pragma unroll 2
    for (int h=0; h<128; h++){
      const float* ar = Ast + h*65 + ty*4;
      const double2* wp2 = (const double2*)(Ws + h*132 + tx*8);
      double2 bA = wp2[0];
      double2 bB = wp2[1];
      double A;
      A = pk2(ar[0]); fmaX2(acc[0],A,bA.x);  fmaX2(acc[1],A,bA.y);  fmaX2(acc[2],A,bB.x);  fmaX2(acc[3],A,bB.y);
      A = pk2(ar[1]); fmaX2(acc[4],A,bA.x);  fmaX2(acc[5],A,bA.y);  fmaX2(acc[6],A,bB.x);  fmaX2(acc[7],A,bB.y);
      A = pk2(ar[2]); fmaX2(acc[8],A,bA.x);  fmaX2(acc[9],A,bA.y);  fmaX2(acc[10],A,bB.x); fmaX2(acc[11],A,bB.y);
      A = pk2(ar[3]); fmaX2(acc[12],A,bA.x); fmaX2(acc[13],A,bA.y); fmaX2(acc[14],A,bB.x); fmaX2(acc[15],A,bB.y);
    }
    // epilogue: bias + LN over 32 k (4 threads share a (node,c)) + affine + mix
    const float* bp = bops + ((size_t)(l*CC + c)*NOPS + o)*KK + kb;
    float wv = g_wmix[(l*CC + c)*NOPS + o];
    #pragma unroll
    for (int i=0;i<4;i++){
      float v[8];
      upk2(acc[i*4+0], v[0], v[1]);
      upk2(acc[i*4+1], v[2], v[3]);
      upk2(acc[i*4+2], v[4], v[5]);
      upk2(acc[i*4+3], v[6], v[7]);
      float s=0.f, sq=0.f;
      #pragma unroll
      for (int j=0;j<8;j++){ float t = v[j] + __ldg(&bp[j]); v[j]=t; s+=t; sq+=t*t; }
      s  += __shfl_xor_sync(0xffffffffu, s, 1);
      sq += __shfl_xor_sync(0xffffffffu, sq, 1);
      s  += __shfl_xor_sync(0xffffffffu, s, 2);
      sq += __shfl_xor_sync(0xffffffffu, sq, 2);
      float mean = s * 0.03125f;
      float var  = sq * 0.03125f - mean*mean;
      float r = rsqrtf(var + 1e-5f);
      #pragma unroll
      for (int j=0;j<8;j++){
        int col = tx*8 + j;
        float nv = (v[j]-mean)*r;
        mixv[i][j] += wv * (nv * s_lg[col] + s_lb[col]);
      }
    }
  }
  #pragma unroll
  for (int i=0;i<4;i++){
    int n = n0 + ty*4 + i;
    if (n < NN){
      float4* yp = (float4*)(g_y + (size_t)n*HH + tx*8);
      yp[0] = make_float4(mixv[i][0],mixv[i][1],mixv[i][2],mixv[i][3]);
      yp[1] = make_float4(mixv[i][4],mixv[i][5],mixv[i][6],mixv[i][7]);
    }
  }
}

// ------------------------- BatchNorm over N (deterministic 2-stage) -------------------------
__global__ void k_bnstat(){
  int t = threadIdx.x; int b = blockIdx.x;
  float s=0.f, sq=0.f;
  for (int r=b; r<NN; r+=BNG){
    float v = g_y[(size_t)r*HH + t];
    s+=v; sq+=v*v;
  }
  g_part[b*HH+t]=s;
  g_part[BNG*HH + b*HH+t]=sq;
}
__global__ void k_bnfin(const float* __restrict__ bng, const float* __restrict__ bnb, int l){
  int t=threadIdx.x;
  float s=0.f, sq=0.f;
  for (int b=0;b<BNG;b++){ s+=g_part[b*HH+t]; sq+=g_part[BNG*HH+b*HH+t]; }
  float mean = s*(1.f/NN);
  float var  = sq*(1.f/NN) - mean*mean;
  float sc = bng[l*HH+t]*rsqrtf(var+1e-5f);
  g_scale[t]=sc;
  g_shift[t]=bnb[l*HH+t]-mean*sc;
}
__global__ void k_bnapply(int l){
  int i = blockIdx.x*blockDim.x+threadIdx.x;
  if (i < NN*32){
    float4 v = ((const float4*)g_y)[i];
    int cb = (i & 31)*4;
    v.x = v.x*g_scale[cb+0]+g_shift[cb+0];
    v.y = v.y*g_scale[cb+1]+g_shift[cb+1];
    v.z = v.z*g_scale[cb+2]+g_shift[cb+2];
    v.w = v.w*g_scale[cb+3]+g_shift[cb+3];
    ((float4*)(g_gr + (size_t)(l+1)*NN*HH))[i] = v;
  }
}

// ------------------------- virtual node MLP -------------------------
__global__ void k_vt(int l){
  int b=blockIdx.x, t=threadIdx.x;
  int s=g_bstart[b], e=g_bstart[b+1];
  float acc=0.f;
  const float* gp = g_gr + (size_t)(l+1)*NN*HH;
  for (int r=s;r<e;r++) acc += gp[(size_t)r*HH+t];
  g_vt[b*HH+t] = acc + g_vn[b*HH+t];
}
__global__ void k_vnl1(const float* __restrict__ W1, const float* __restrict__ b1, int l){
  __shared__ float vr[HH];
  int row=blockIdx.x, t=threadIdx.x;
  if (t<HH) vr[t]=g_vt[row*HH+t];
  __syncthreads();
  float acc = b1[l*2*HH+t];
  const float* w = W1 + (size_t)l*HH*2*HH + t;
  #pragma unroll 4
  for (int h=0;h<HH;h++) acc += vr[h]*w[h*2*HH];
  g_h1[row*2*HH+t]=acc;
}
__global__ void k_vnbn1(const float* __restrict__ g, const float* __restrict__ bb, int l){
  int t=threadIdx.x;
  float s=0.f, sq=0.f;
  for (int r=0;r<NB;r++){ float v=g_h1[r*2*HH+t]; s+=v; sq+=v*v; }
  float mean=s*(1.f/NB);
  float var=sq*(1.f/NB)-mean*mean;
  float rs=rsqrtf(var+1e-5f);
  float gam=g[l*2*HH+t], bet=bb[l*2*HH+t];
  for (int r=0;r<NB;r++){
    float v=g_h1[r*2*HH+t];
    v=(v-mean)*rs*gam+bet;
    g_h1[r*2*HH+t] = v>0.f? v:0.f;
  }
}
__global__ void k_vnl2(const float* __restrict__ W2, const float* __restrict__ b2, int l){
  __shared__ float hr[2*HH];
  int row=blockIdx.x, t=threadIdx.x;
  hr[t]=g_h1[row*2*HH+t];
  hr[t+HH]=g_h1[row*2*HH+t+HH];
  __syncthreads();
  float acc = b2[l*HH+t];
  const float* w = W2 + (size_t)l*2*HH*HH + t;
  #pragma unroll 4
  for (int h=0;h<2*HH;h++) acc += hr[h]*w[h*HH];
  g_h2[row*HH+t]=acc;
}
__global__ void k_vnbn2(const float* __restrict__ g, const float* __restrict__ bb, int l){
  int t=threadIdx.x;
  float s=0.f, sq=0.f;
  for (int r=0;r<NB;r++){ float v=g_h2[r*HH+t]; s+=v; sq+=v*v; }
  float mean=s*(1.f/NB);
  float var=sq*(1.f/NB)-mean*mean;
  float rs=rsqrtf(var+1e-5f);
  float gam=g[l*HH+t], bet=bb[l*HH+t];
  for (int r=0;r<NB;r++){
    float v=g_h2[r*HH+t];
    v=(v-mean)*rs*gam+bet;
    g_vn[r*HH+t] = v>0.f? v:0.f;
  }
}

// ------------------------- pooling + head -------------------------
__global__ void k_pool(){
  int b=blockIdx.x, t=threadIdx.x;
  int s=g_bstart[b], e=g_bstart[b+1];
  float inv = 1.f/(float)max(e-s,1);
  for (int st=0; st<4; st++){
    const float* gp = g_gr + (size_t)st*NN*HH;
    float sum=0.f, mx=-1e30f;
    for (int r=s;r<e;r++){ float v=gp[(size_t)r*HH+t]; sum+=v; mx=fmaxf(mx,v); }
    if (e==s) mx=0.f;
    g_pooled[b*1024 + st*HH + t] = sum*inv;
    g_pooled[b*1024 + 512 + st*HH + t] = mx;
  }
}
__global__ void k_head(const float* __restrict__ hW, const float* __restrict__ hb,
                       const float* __restrict__ hM, float* __restrict__ out){
  __shared__ float red[NOUT];
  int b=blockIdx.x, t=threadIdx.x;
  if (t<NOUT) red[t]=0.f;
  __syncthreads();
  float acc[NOUT];
  #pragma unroll
  for (int j=0;j<NOUT;j++) acc[j]=0.f;
  for (int d=t; d<1024; d+=256){
    float pv = g_pooled[b*1024+d];
    const float* wrow = hW + d*NOUT;
    const float* mrow = hM + d*NOUT;
    #pragma unroll
    for (int j=0;j<NOUT;j++) acc[j] += pv*wrow[j]*mrow[j];
  }
  #pragma unroll
  for (int j=0;j<NOUT;j++) atomicAdd(&red[j], acc[j]);
  __syncthreads();
  if (t<NOUT) out[b*NOUT+t] = red[t] + hb[t];
}

// ------------------------- launch -------------------------
extern "C" void kernel_launch(void* const* d_in, const int* in_sizes, int n_in,
                              void* d_out, int out_size){
  const float* x      = (const float*)d_in[0];
  const int*   ei     = (const int*)d_in[1];
  const int*   batch  = (const int*)d_in[2];
  const float* lin1W  = (const float*)d_in[3];
  const float* lin1b  = (const float*)d_in[4];
  const float* vn0    = (const float*)d_in[5];
  const float* Wops   = (const float*)d_in[6];
  const float* bops   = (const float*)d_in[7];
  const float* atta   = (const float*)d_in[8];
  const float* lng    = (const float*)d_in[9];
  const float* lnb    = (const float*)d_in[10];
  const float* bng    = (const float*)d_in[11];
  const float* bnb    = (const float*)d_in[12];
  const float* vnW1   = (const float*)d_in[13];
  const float* vnb1   = (const float*)d_in[14];
  const float* vnbn1g = (const float*)d_in[15];
  const float* vnbn1b = (const float*)d_in[16];
  const float* vnW2   = (const float*)d_in[17];
  const float* vnb2   = (const float*)d_in[18];
  const float* vnbn2g = (const float*)d_in[19];
  const float* vnbn2b = (const float*)d_in[20];
  const float* alphas = (const float*)d_in[21];
  const float* headW  = (const float*)d_in[22];
  const float* headb  = (const float*)d_in[23];
  const float* headM  = (const float*)d_in[24];
  float* out = (float*)d_out;
  const int* src = ei;
  const int* dst = ei + NE;

  cudaFuncSetAttribute(k_mix, cudaFuncAttributeMaxDynamicSharedMemorySize, SMEM_MIX);

  const int NBLK = (NN + 255)/256;          // 196
  const int WBLK = (NN*32 + 255)/256;       // 6250
  const int EBLK = (NE + 255)/256;          // 3125
  const int MIXBLK = (NN + 63)/64;          // 782

  // CSR + prep
  k_zero_deg<<<NBLK,256>>>();
  k_count<<<EBLK,256>>>(dst);
  k_scan<<<1,1024>>>();
  k_nodeprep<<<NBLK,256>>>();
  k_scatter<<<EBLK,256>>>(src, dst);
  k_bstart<<<NBLK,256>>>(batch);
  k_prepw<<<1,32>>>(alphas);
  k_vninit<<<(NB*HH+255)/256,256>>>(vn0);

  // encoder
  k_lin1<<<(NN+15)/16,128>>>(x, lin1W, lin1b);

  for (int l=0; l<LL; l++){
    k_nodeA<<<WBLK,256>>>(batch, atta, l);
    k_att<<<NBLK,256>>>();
    k_gather<<<WBLK,256>>>();
    k_mix<<<MIXBLK,256,SMEM_MIX>>>(l, Wops, bops, lng, lnb);
    k_bnstat<<<BNG,128>>>();
    k_bnfin<<<1,128>>>(bng, bnb, l);
    k_bnapply<<<(NN*32+255)/256,256>>>(l);
    if (l < LL-1){
      k_vt<<<NB,128>>>(l);
      k_vnl1<<<NB,256>>>(vnW1, vnb1, l);
      k_vnbn1<<<1,256>>>(vnbn1g, vnbn1b, l);
      k_vnl2<<<NB,128>>>(vnW2, vnb2, l);
      k_vnbn2<<<1,128>>>(vnbn2g, vnbn2b, l);
    }
  }
  k_pool<<<NB,128>>>();
  k_head<<<NB,256>>>(headW, headb, headM, out);
}

// round 4
// speedup vs baseline: 1.8136x; 1.8136x over previous
#include <cuda_runtime.h>
#include <cuda_bf16.h>
#include <math.h>
#include <stdint.h>

#define NN 50000
#define NE 800000
#define FIN 64
#define HH 128
#define LL 3
#define CC 4
#define KK 32
#define NOPS 7
#define NB 512
#define NOUT 10
#define BNG 400

// ------------------------- device scratch (no allocs) -------------------------
__device__ float g_gr[(LL+1)*NN*HH];
__device__ float g_xw[NN*HH];
__device__ float g_sum[NN*HH];
__device__ float g_nrm[NN*HH];
__device__ float g_att[NN*HH];
__device__ float g_y[NN*HH];
__device__ float g_s0[NN];
__device__ float g_s1[NN];
__device__ float g_sinv[NN];
__device__ float g_dinv[NN];
__device__ float g_minv[NN];
__device__ float g_eedge[NE];
__device__ int   g_deg[NN];
__device__ int   g_rowptr[NN+1];
__device__ int   g_cursor[NN];
__device__ int   g_csrsrc[NE];
__device__ int   g_bstart[NB+1];
__device__ float g_wmix[LL*CC*NOPS];
__device__ float g_vn[NB*HH];
__device__ float g_vt[NB*HH];
__device__ float g_h1[NB*2*HH];
__device__ float g_h2[NB*HH];
__device__ float g_part[2*BNG*HH];
__device__ float g_scale[HH];
__device__ float g_shift[HH];
__device__ float g_pooled[NB*8*HH];
// W transposed to [outcol n=c*32+k][h], bf16 hi/lo split, per (l,o)
__device__ unsigned short g_Whi[LL*NOPS*16384];
__device__ unsigned short g_Wlo[LL*NOPS*16384];

// ------------------------- PTX helpers (baseline ISA, sm_80+) -------------------------
__device__ __forceinline__ uint32_t smem_u32(const void* p){
  uint32_t a; asm("{ .reg .u64 t; cvta.to.shared.u64 t, %1; cvt.u32.u64 %0, t; }" : "=r"(a) : "l"(p));
  return a;
}
__device__ __forceinline__ void ldsm4(uint32_t &r0, uint32_t &r1, uint32_t &r2, uint32_t &r3, uint32_t addr){
  asm volatile("ldmatrix.sync.aligned.m8n8.x4.shared.b16 {%0,%1,%2,%3}, [%4];"
    : "=r"(r0), "=r"(r1), "=r"(r2), "=r"(r3) : "r"(addr));
}
__device__ __forceinline__ void mma16816(float* d, const uint32_t* a, const uint32_t* b){
  asm volatile("mma.sync.aligned.m16n8k16.row.col.f32.bf16.bf16.f32 "
    "{%0,%1,%2,%3}, {%4,%5,%6,%7}, {%8,%9}, {%0,%1,%2,%3};"
    : "+f"(d[0]), "+f"(d[1]), "+f"(d[2]), "+f"(d[3])
    : "r"(a[0]), "r"(a[1]), "r"(a[2]), "r"(a[3]), "r"(b[0]), "r"(b[1]));
}

// ------------------------- CSR build -------------------------
__global__ void k_zero_deg(){
  int i = blockIdx.x*blockDim.x + threadIdx.x;
  if (i < NN) g_deg[i] = 0;
}
__global__ void k_count(const int* __restrict__ dst){
  int e = blockIdx.x*blockDim.x + threadIdx.x;
  if (e < NE) atomicAdd(&g_deg[dst[e]], 1);
}
__global__ void k_scan(){
  __shared__ int sm[1024];
  const int CH = (NN + 1023)/1024;
  int t = threadIdx.x;
  int s = 0;
  for (int i=0;i<CH;i++){ int idx = t*CH+i; if (idx<NN) s += g_deg[idx]; }
  sm[t] = s; __syncthreads();
  for (int off=1; off<1024; off<<=1){
    int v = (t>=off) ? sm[t-off] : 0;
    __syncthreads();
    if (t>=off) sm[t] += v;
    __syncthreads();
  }
  int run = (t>0)? sm[t-1] : 0;
  for (int i=0;i<CH;i++){ int idx=t*CH+i; if (idx<NN){ g_rowptr[idx]=run; run += g_deg[idx]; } }
  if (t==1023) g_rowptr[NN] = sm[1023];
}
__global__ void k_nodeprep(){
  int i = blockIdx.x*blockDim.x + threadIdx.x;
  if (i < NN){
    g_cursor[i] = g_rowptr[i];
    float dc = (float)max(g_deg[i], 1);
    g_dinv[i] = rsqrtf(dc);
    g_minv[i] = 1.f/dc;
  }
}
__global__ void k_scatter(const int* __restrict__ src, const int* __restrict__ dst){
  int e = blockIdx.x*blockDim.x + threadIdx.x;
  if (e < NE){
    int slot = atomicAdd(&g_cursor[dst[e]], 1);
    g_csrsrc[slot] = src[e];
  }
}
__global__ void k_bstart(const int* __restrict__ batch){
  int i = blockIdx.x*blockDim.x + threadIdx.x;
  if (i >= NN) return;
  int b = batch[i];
  if (i == 0){ for (int bb=0; bb<=b; bb++) g_bstart[bb] = 0; }
  else { int p = batch[i-1]; for (int bb=p+1; bb<=b; bb++) g_bstart[bb] = i; }
  if (i == NN-1){ for (int bb=b+1; bb<=NB; bb++) g_bstart[bb] = NN; }
}
__global__ void k_prepw(const float* __restrict__ alphas){
  int g = threadIdx.x;
  if (g < LL*CC){
    const float* a = alphas + g*NOPS;
    float mx = a[0];
    for (int o=1;o<NOPS;o++) mx = fmaxf(mx, a[o]);
    float e[NOPS]; float s = 0.f;
    for (int o=0;o<NOPS;o++){ e[o] = expf(a[o]-mx); s += e[o]; }
    for (int o=0;o<NOPS;o++) g_wmix[g*NOPS+o] = e[o]/s;
  }
}
__global__ void k_vninit(const float* __restrict__ vn0){
  int i = blockIdx.x*blockDim.x + threadIdx.x;
  if (i < NB*HH) g_vn[i] = vn0[i & (HH-1)];
}

// ------------------------- weight prep: transpose + bf16 split -------------------------
__global__ void k_wprep(const float* __restrict__ Wops){
  int idx = blockIdx.x*blockDim.x + threadIdx.x;
  if (idx >= LL*NOPS*16384) return;
  int lop = idx >> 14;          // l*NOPS + o
  int el  = idx & 16383;
  int l = lop / NOPS, o = lop % NOPS;
  int r = el >> 7;              // out col index n = c*32+k
  int h = el & 127;             // contraction dim
  int c = r >> 5, k = r & 31;
  float w = Wops[(((size_t)(l*CC + c)*NOPS + o)*HH + h)*KK + k];
  __nv_bfloat16 hb = __float2bfloat16(w);
  float res = w - __bfloat162float(hb);
  __nv_bfloat16 lb = __float2bfloat16(res);
  g_Whi[(size_t)lop*16384 + r*128 + h] = __bfloat16_as_ushort(hb);
  g_Wlo[(size_t)lop*16384 + r*128 + h] = __bfloat16_as_ushort(lb);
}

// ------------------------- lin1 + ELU -------------------------
__global__ void __launch_bounds__(128) k_lin1(const float* __restrict__ x,
    const float* __restrict__ W, const float* __restrict__ bias){
  __shared__ float Wt[HH*68];
  __shared__ float xs[16][FIN];
  int tid = threadIdx.x;
  for (int i=tid; i<FIN*HH; i+=128){ int h=i>>7, c=i&127; Wt[c*68+h] = W[i]; }
  int n0 = blockIdx.x*16;
  for (int i=tid; i<16*FIN; i+=128){
    int nl=i>>6, h=i&63; int n=n0+nl;
    xs[nl][h] = (n<NN)? x[n*FIN+h] : 0.f;
  }
  __syncthreads();
  float acc[16];
  float bv = bias[tid];
  #pragma unroll
  for (int nl=0;nl<16;nl++) acc[nl]=bv;
  #pragma unroll
  for (int h4=0; h4<FIN/4; h4++){
    float4 w4 = *(const float4*)&Wt[tid*68 + h4*4];
    #pragma unroll
    for (int nl=0;nl<16;nl++){
      float4 x4 = *(const float4*)&xs[nl][h4*4];
      acc[nl] += w4.x*x4.x + w4.y*x4.y + w4.z*x4.z + w4.w*x4.w;
    }
  }
  #pragma unroll
  for (int nl=0;nl<16;nl++){
    int n = n0+nl;
    if (n<NN){
      float a = acc[nl];
      a = a>0.f ? a : expm1f(a);
      g_gr[(size_t)n*HH+tid] = a;
    }
  }
}

// ------------------------- per-layer node prep -------------------------
__global__ void k_nodeA(const int* __restrict__ batch, const float* __restrict__ atta, int l){
  int w = (blockIdx.x*blockDim.x + threadIdx.x) >> 5;
  int lane = threadIdx.x & 31;
  if (w >= NN) return;
  int b = batch[w];
  float4 xv = ((const float4*)(g_gr + (size_t)l*NN*HH))[w*32 + lane];
  float4 vv = ((const float4*)g_vn)[b*32 + lane];
  xv.x += vv.x; xv.y += vv.y; xv.z += vv.z; xv.w += vv.w;
  ((float4*)g_xw)[w*32 + lane] = xv;
  float4 a0 = ((const float4*)(atta + l*2*HH))[lane];
  float4 a1 = ((const float4*)(atta + l*2*HH + HH))[lane];
  float s0 = xv.x*a0.x + xv.y*a0.y + xv.z*a0.z + xv.w*a0.w;
  float s1 = xv.x*a1.x + xv.y*a1.y + xv.z*a1.z + xv.w*a1.w;
  #pragma unroll
  for (int off=16; off; off>>=1){
    s0 += __shfl_xor_sync(0xffffffffu, s0, off);
    s1 += __shfl_xor_sync(0xffffffffu, s1, off);
  }
  if (lane==0){ g_s0[w]=s0; g_s1[w]=s1; }
}

__global__ void k_att(){
  int n = blockIdx.x*blockDim.x + threadIdx.x;
  if (n >= NN) return;
  int s = g_rowptr[n], e = g_rowptr[n+1];
  float s1v = g_s1[n];
  float m = -1e30f;
  for (int j=s;j<e;j++){
    float ev = g_s0[g_csrsrc[j]] + s1v;
    ev = ev>0.f ? ev : 0.2f*ev;
    g_eedge[j]=ev;
    m = fmaxf(m,ev);
  }
  if (e==s) m = 0.f;
  float ss=0.f;
  for (int j=s;j<e;j++){
    float p = expf(g_eedge[j]-m);
    g_eedge[j]=p;
    ss+=p;
  }
  g_sinv[n] = 1.f/(ss+1e-16f);
}

__global__ void k_gather(){
  int w = (blockIdx.x*blockDim.x + threadIdx.x) >> 5;
  int lane = threadIdx.x & 31;
  if (w >= NN) return;
  int s = g_rowptr[w], e = g_rowptr[w+1];
  float dv = g_dinv[w];
  float si = g_sinv[w];
  float4 a_s = make_float4(0.f,0.f,0.f,0.f);
  float4 a_n = a_s, a_a = a_s;
  for (int j=s; j<e; j++){
    int sn = g_csrsrc[j];
    float p  = g_eedge[j];
    float nw = g_dinv[sn]*dv;
    float ca = p*si;
    float4 xv = ((const float4*)g_xw)[sn*32 + lane];
    a_s.x+=xv.x;      a_s.y+=xv.y;      a_s.z+=xv.z;      a_s.w+=xv.w;
    a_n.x+=nw*xv.x;   a_n.y+=nw*xv.y;   a_n.z+=nw*xv.z;   a_n.w+=nw*xv.w;
    a_a.x+=ca*xv.x;   a_a.y+=ca*xv.y;   a_a.z+=ca*xv.z;   a_a.w+=ca*xv.w;
  }
  ((float4*)g_sum)[w*32+lane]=a_s;
  ((float4*)g_nrm)[w*32+lane]=a_n;
  ((float4*)g_att)[w*32+lane]=a_a;
}

// ------------------------- warp-MMA mixed-op GEMM + LN + DARTS mix -------------------------
// block = 128 nodes x 128 outcols, K=128. 8 warps, warp w owns rows w*16..w*16+15.
// bf16 hi/lo split (3 products) into f32 accum. Epilogue fully in registers.
#define PADK 136
#define SM_AHI 0
#define SM_ALO (128*PADK*2)
#define SM_WHI (2*128*PADK*2)
#define SM_WLO (3*128*PADK*2)
#define SM_BB  (4*128*PADK*2)
#define SM_LG  (SM_BB+512)
#define SM_LB  (SM_LG+512)
#define SMEM_MIX (SM_LB+512)

__constant__ int c_opseq[7] = {0,5,1,2,3,4,6};
__constant__ int c_asel[7]  = {0,0,1,2,3,4,5};

__global__ void __launch_bounds__(256,1) k_mix_mma(int l,
    const float* __restrict__ bops, const float* __restrict__ lng, const float* __restrict__ lnb){
  extern __shared__ char smc[];
  uint32_t sbase = smem_u32(smc);
  float* s_bb = (float*)(smc + SM_BB);
  float* s_lg = (float*)(smc + SM_LG);
  float* s_lb = (float*)(smc + SM_LB);
  int tid = threadIdx.x;
  int lane = tid & 31, w = tid >> 5;
  int g = lane >> 2, tig = lane & 3;
  int n0 = blockIdx.x * 128;
  if (tid < 128){ s_lg[tid] = lng[l*128+tid]; s_lb[tid] = lnb[l*128+tid]; }

  // ldmatrix lane address offsets (in bf16 elements)
  int a_off = ((lane&7) + ((lane>>3)&1)*8)*PADK + (lane>>4)*8;
  int b_off = (((lane>>4)&1)*8 + (lane&7))*PADK + ((lane>>3)&1)*8;
  uint32_t AbH = sbase + SM_AHI + (uint32_t)(w*16*PADK + a_off)*2;
  uint32_t AbL = sbase + SM_ALO + (uint32_t)(w*16*PADK + a_off)*2;
  uint32_t WbH = sbase + SM_WHI + (uint32_t)b_off*2;
  uint32_t WbL = sbase + SM_WLO + (uint32_t)b_off*2;

  float mix[16][4];
  #pragma unroll
  for (int f=0;f<16;f++){ mix[f][0]=0.f; mix[f][1]=0.f; mix[f][2]=0.f; mix[f][3]=0.f; }

  int prevA = -1;
  for (int oi=0; oi<7; oi++){
    int o = c_opseq[oi], asel = c_asel[oi];
    __syncthreads();
    if (asel != prevA){
      prevA = asel;
      #pragma unroll 1
      for (int it=0; it<32; it++){
        int wi = it*256 + tid;          // word index 0..8191
        int r = wi >> 6;
        int h0 = (wi & 63)*2;
        int n = n0 + r;
        float vx=0.f, vy=0.f;
        if (n < NN){
          size_t base = (size_t)n*HH + h0;
          if (asel==0){ float2 a = *(const float2*)(g_nrm+base); vx=a.x; vy=a.y; }
          else if (asel==1){ float2 a=*(const float2*)(g_xw+base); float2 bq=*(const float2*)(g_sum+base); vx=a.x+bq.x; vy=a.y+bq.y; }
          else if (asel==2){ float2 a=*(const float2*)(g_att+base); vx=a.x; vy=a.y; }
          else if (asel==3){ float2 a=*(const float2*)(g_xw+base); float2 bq=*(const float2*)(g_sum+base); float m=g_minv[n]; vx=a.x+bq.x*m; vy=a.y+bq.y*m; }
          else if (asel==4){ float2 bq=*(const float2*)(g_sum+base); float m=g_minv[n]; vx=bq.x*m; vy=bq.y*m; }
          else { float2 a=*(const float2*)(g_xw+base); vx=a.x; vy=a.y; }
        }
        __nv_bfloat16 hx = __float2bfloat16(vx);
        __nv_bfloat16 hy = __float2bfloat16(vy);
        __nv_bfloat16 lx = __float2bfloat16(vx - __bfloat162float(hx));
        __nv_bfloat16 ly = __float2bfloat16(vy - __bfloat162float(hy));
        uint32_t off = (uint32_t)(r*PADK + h0)*2;
        *(uint32_t*)(smc + SM_AHI + off) = (uint32_t)__bfloat16_as_ushort(hx) | ((uint32_t)__bfloat16_as_ushort(hy)<<16);
        *(uint32_t*)(smc + SM_ALO + off) = (uint32_t)__bfloat16_as_ushort(lx) | ((uint32_t)__bfloat16_as_ushort(ly)<<16);
      }
    }
    // W tiles -> smem (with PADK padding)
    {
      const uint4* srcH = (const uint4*)(g_Whi + (size_t)(l*NOPS+o)*16384);
      const uint4* srcL = (const uint4*)(g_Wlo + (size_t)(l*NOPS+o)*16384);
      #pragma unroll
      for (int it=0; it<8; it++){
        int i = it*256 + tid;
        int row = i >> 4, q = i & 15;
        uint32_t off = (uint32_t)(row*PADK + q*8)*2;
        *(uint4*)(smc + SM_WHI + off) = srcH[i];
        *(uint4*)(smc + SM_WLO + off) = srcL[i];
      }
    }
    if (tid < 128){
      int c = tid>>5, k = tid&31;
      s_bb[tid] = bops[((size_t)(l*CC + c)*NOPS + o)*KK + k];
    }
    __syncthreads();

    float acc[16][4];
    #pragma unroll
    for (int f=0;f<16;f++){ acc[f][0]=0.f; acc[f][1]=0.f; acc[f][2]=0.f; acc[f][3]=0.f; }
    #pragma unroll 1
    for (int ks=0; ks<8; ks++){
      uint32_t k0b = (uint32_t)(ks*16)*2;
      uint32_t ah[4], al[4];
      ldsm4(ah[0],ah[1],ah[2],ah[3], AbH + k0b);
      ldsm4(al[0],al[1],al[2],al[3], AbL + k0b);
      #pragma unroll
      for (int nfp=0; nfp<8; nfp++){
        uint32_t bh[4], bl[4];
        uint32_t woff = (uint32_t)(nfp*16*PADK)*2 + k0b;
        ldsm4(bh[0],bh[1],bh[2],bh[3], WbH + woff);
        ldsm4(bl[0],bl[1],bl[2],bl[3], WbL + woff);
        mma16816(acc[2*nfp],   ah, bh);
        mma16816(acc[2*nfp],   ah, bl);
        mma16816(acc[2*nfp],   al, bh);
        mma16816(acc[2*nfp+1], ah, bh+2);
        mma16816(acc[2*nfp+1], ah, bl+2);
        mma16816(acc[2*nfp+1], al, bh+2);
      }
    }
    // epilogue: bias + LayerNorm(32) per (row, c) + affine + DARTS mix
    #pragma unroll
    for (int c=0; c<4; c++){
      float tv[4][4];
      float sA=0.f, sqA=0.f, sB=0.f, sqB=0.f;
      #pragma unroll
      for (int fi=0; fi<4; fi++){
        int f = 4*c + fi;
        int col0 = f*8 + 2*tig;
        float b0 = s_bb[col0], b1 = s_bb[col0+1];
        float t0 = acc[f][0]+b0, t1 = acc[f][1]+b1;
        float t2 = acc[f][2]+b0, t3 = acc[f][3]+b1;
        tv[fi][0]=t0; tv[fi][1]=t1; tv[fi][2]=t2; tv[fi][3]=t3;
        sA += t0+t1; sqA += t0*t0+t1*t1;
        sB += t2+t3; sqB += t2*t2+t3*t3;
      }
      sA += __shfl_xor_sync(0xffffffffu, sA, 1);  sqA += __shfl_xor_sync(0xffffffffu, sqA, 1);
      sB += __shfl_xor_sync(0xffffffffu, sB, 1);  sqB += __shfl_xor_sync(0xffffffffu, sqB, 1);
      sA += __shfl_xor_sync(0xffffffffu, sA, 2);  sqA += __shfl_xor_sync(0xffffffffu, sqA, 2);
      sB += __shfl_xor_sync(0xffffffffu, sB, 2);  sqB += __shfl_xor_sync(0xffffffffu, sqB, 2);
      float mA = sA*(1.f/32.f), vA = sqA*(1.f/32.f) - mA*mA;
      float mB = sB*(1.f/32.f), vB = sqB*(1.f/32.f) - mB*mB;
      float rA = rsqrtf(vA + 1e-5f), rB = rsqrtf(vB + 1e-5f);
      float wv = g_wmix[(l*CC + c)*NOPS + o];
      #pragma unroll
      for (int fi=0; fi<4; fi++){
        int f = 4*c + fi;
        int col0 = f*8 + 2*tig;
        float lg0=s_lg[col0], lg1=s_lg[col0+1], lb0=s_lb[col0], lb1=s_lb[col0+1];
        mix[f][0] += wv*((tv[fi][0]-mA)*rA*lg0 + lb0);
        mix[f][1] += wv*((tv[fi][1]-mA)*rA*lg1 + lb1);
        mix[f][2] += wv*((tv[fi][2]-mB)*rB*lg0 + lb0);
        mix[f][3] += wv*((tv[fi][3]-mB)*rB*lg1 + lb1);
      }
    }
  }
  // write out
  int rA = n0 + w*16 + g;
  int rB = rA + 8;
  #pragma unroll
  for (int f=0; f<16; f++){
    int col = f*8 + 2*tig;
    if (rA < NN) *(float2*)&g_y[(size_t)rA*HH + col] = make_float2(mix[f][0], mix[f][1]);
    if (rB < NN) *(float2*)&g_y[(size_t)rB*HH + col] = make_float2(mix[f][2], mix[f][3]);
  }
}

// ------------------------- BatchNorm over N (deterministic 2-stage) -------------------------
__global__ void k_bnstat(){
  int t = threadIdx.x; int b = blockIdx.x;
  float s=0.f, sq=0.f;
  for (int r=b; r<NN; r+=BNG){
    float v = g_y[(size_t)r*HH + t];
    s+=v; sq+=v*v;
  }
  g_part[b*HH+t]=s;
  g_part[BNG*HH + b*HH+t]=sq;
}
__global__ void k_bnfin(const float* __restrict__ bng, const float* __restrict__ bnb, int l){
  int t=threadIdx.x;
  float s=0.f, sq=0.f;
  for (int b=0;b<BNG;b++){ s+=g_part[b*HH+t]; sq+=g_part[BNG*HH+b*HH+t]; }
  float mean = s*(1.f/NN);
  float var  = sq*(1.f/NN) - mean*mean;
  float sc = bng[l*HH+t]*rsqrtf(var+1e-5f);
  g_scale[t]=sc;
  g_shift[t]=bnb[l*HH+t]-mean*sc;
}
__global__ void k_bnapply(int l){
  int i = blockIdx.x*blockDim.x+threadIdx.x;
  if (i < NN*32){
    float4 v = ((const float4*)g_y)[i];
    int cb = (i & 31)*4;
    v.x = v.x*g_scale[cb+0]+g_shift[cb+0];
    v.y = v.y*g_scale[cb+1]+g_shift[cb+1];
    v.z = v.z*g_scale[cb+2]+g_shift[cb+2];
    v.w = v.w*g_scale[cb+3]+g_shift[cb+3];
    ((float4*)(g_gr + (size_t)(l+1)*NN*HH))[i] = v;
  }
}

// ------------------------- virtual node MLP -------------------------
__global__ void k_vt(int l){
  int b=blockIdx.x, t=threadIdx.x;
  int s=g_bstart[b], e=g_bstart[b+1];
  float acc=0.f;
  const float* gp = g_gr + (size_t)(l+1)*NN*HH;
  for (int r=s;r<e;r++) acc += gp[(size_t)r*HH+t];
  g_vt[b*HH+t] = acc + g_vn[b*HH+t];
}
__global__ void k_vnl1(const float* __restrict__ W1, const float* __restrict__ b1, int l){
  __shared__ float vr[HH];
  int row=blockIdx.x, t=threadIdx.x;
  if (t<HH) vr[t]=g_vt[row*HH+t];
  __syncthreads();
  float acc = b1[l*2*HH+t];
  const float* w = W1 + (size_t)l*HH*2*HH + t;
  #pragma unroll 4
  for (int h=0;h<HH;h++) acc += vr[h]*w[h*2*HH];
  g_h1[row*2*HH+t]=acc;
}
__global__ void k_vnbn1(const float* __restrict__ g, const float* __restrict__ bb, int l){
  int t=threadIdx.x;
  float s=0.f, sq=0.f;
  for (int r=0;r<NB;r++){ float v=g_h1[r*2*HH+t]; s+=v; sq+=v*v; }
  float mean=s*(1.f/NB);
  float var=sq*(1.f/NB)-mean*mean;
  float rs=rsqrtf(var+1e-5f);
  float gam=g[l*2*HH+t], bet=bb[l*2*HH+t];
  for (int r=0;r<NB;r++){
    float v=g_h1[r*2*HH+t];
    v=(v-mean)*rs*gam+bet;
    g_h1[r*2*HH+t] = v>0.f? v:0.f;
  }
}
__global__ void k_vnl2(const float* __restrict__ W2, const float* __restrict__ b2, int l){
  __shared__ float hr[2*HH];
  int row=blockIdx.x, t=threadIdx.x;
  hr[t]=g_h1[row*2*HH+t];
  hr[t+HH]=g_h1[row*2*HH+t+HH];
  __syncthreads();
  float acc = b2[l*HH+t];
  const float* w = W2 + (size_t)l*2*HH*HH + t;
  #pragma unroll 4
  for (int h=0;h<2*HH;h++) acc += hr[h]*w[h*HH];
  g_h2[row*HH+t]=acc;
}
__global__ void k_vnbn2(const float* __restrict__ g, const float* __restrict__ bb, int l){
  int t=threadIdx.x;
  float s=0.f, sq=0.f;
  for (int r=0;r<NB;r++){ float v=g_h2[r*HH+t]; s+=v; sq+=v*v; }
  float mean=s*(1.f/NB);
  float var=sq*(1.f/NB)-mean*mean;
  float rs=rsqrtf(var+1e-5f);
  float gam=g[l*HH+t], bet=bb[l*HH+t];
  for (int r=0;r<NB;r++){
    float v=g_h2[r*HH+t];
    v=(v-mean)*rs*gam+bet;
    g_vn[r*HH+t] = v>0.f? v:0.f;
  }
}

// ------------------------- pooling + head -------------------------
__global__ void k_pool(){
  int b=blockIdx.x, t=threadIdx.x;
  int s=g_bstart[b], e=g_bstart[b+1];
  float inv = 1.f/(float)max(e-s,1);
  for (int st=0; st<4; st++){
    const float* gp = g_gr + (size_t)st*NN*HH;
    float sum=0.f, mx=-1e30f;
    for (int r=s;r<e;r++){ float v=gp[(size_t)r*HH+t]; sum+=v; mx=fmaxf(mx,v); }
    if (e==s) mx=0.f;
    g_pooled[b*1024 + st*HH + t] = sum*inv;
    g_pooled[b*1024 + 512 + st*HH + t] = mx;
  }
}
__global__ void k_head(const float* __restrict__ hW, const float* __restrict__ hb,
                       const float* __restrict__ hM, float* __restrict__ out){
  __shared__ float red[NOUT];
  int b=blockIdx.x, t=threadIdx.x;
  if (t<NOUT) red[t]=0.f;
  __syncthreads();
  float acc[NOUT];
  #pragma unroll
  for (int j=0;j<NOUT;j++) acc[j]=0.f;
  for (int d=t; d<1024; d+=256){
    float pv = g_pooled[b*1024+d];
    const float* wrow = hW + d*NOUT;
    const float* mrow = hM + d*NOUT;
    #pragma unroll
    for (int j=0;j<NOUT;j++) acc[j] += pv*wrow[j]*mrow[j];
  }
  #pragma unroll
  for (int j=0;j<NOUT;j++) atomicAdd(&red[j], acc[j]);
  __syncthreads();
  if (t<NOUT) out[b*NOUT+t] = red[t] + hb[t];
}

// ------------------------- launch -------------------------
extern "C" void kernel_launch(void* const* d_in, const int* in_sizes, int n_in,
                              void* d_out, int out_size){
  const float* x      = (const float*)d_in[0];
  const int*   ei     = (const int*)d_in[1];
  const int*   batch  = (const int*)d_in[2];
  const float* lin1W  = (const float*)d_in[3];
  const float* lin1b  = (const float*)d_in[4];
  const float* vn0    = (const float*)d_in[5];
  const float* Wops   = (const float*)d_in[6];
  const float* bops   = (const float*)d_in[7];
  const float* atta   = (const float*)d_in[8];
  const float* lng    = (const float*)d_in[9];
  const float* lnb    = (const float*)d_in[10];
  const float* bng    = (const float*)d_in[11];
  const float* bnb    = (const float*)d_in[12];
  const float* vnW1   = (const float*)d_in[13];
  const float* vnb1   = (const float*)d_in[14];
  const float* vnbn1g = (const float*)d_in[15];
  const float* vnbn1b = (const float*)d_in[16];
  const float* vnW2   = (const float*)d_in[17];
  const float* vnb2   = (const float*)d_in[18];
  const float* vnbn2g = (const float*)d_in[19];
  const float* vnbn2b = (const float*)d_in[20];
  const float* alphas = (const float*)d_in[21];
  const float* headW  = (const float*)d_in[22];
  const float* headb  = (const float*)d_in[23];
  const float* headM  = (const float*)d_in[24];
  float* out = (float*)d_out;
  const int* src = ei;
  const int* dst = ei + NE;

  cudaFuncSetAttribute(k_mix_mma, cudaFuncAttributeMaxDynamicSharedMemorySize, SMEM_MIX);

  const int NBLK = (NN + 255)/256;
  const int WBLK = (NN*32 + 255)/256;
  const int EBLK = (NE + 255)/256;
  const int MIXBLK = (NN + 127)/128;   // 391

  k_zero_deg<<<NBLK,256>>>();
  k_count<<<EBLK,256>>>(dst);
  k_scan<<<1,1024>>>();
  k_nodeprep<<<NBLK,256>>>();
  k_scatter<<<EBLK,256>>>(src, dst);
  k_bstart<<<NBLK,256>>>(batch);
  k_prepw<<<1,32>>>(alphas);
  k_vninit<<<(NB*HH+255)/256,256>>>(vn0);
  k_wprep<<<(LL*NOPS*16384+255)/256,256>>>(Wops);

  k_lin1<<<(NN+15)/16,128>>>(x, lin1W, lin1b);

  for (int l=0; l<LL; l++){
    k_nodeA<<<WBLK,256>>>(batch, atta, l);
    k_att<<<NBLK,256>>>();
    k_gather<<<WBLK,256>>>();
    k_mix_mma<<<MIXBLK,256,SMEM_MIX>>>(l, bops, lng, lnb);
    k_bnstat<<<BNG,128>>>();
    k_bnfin<<<1,128>>>(bng, bnb, l);
    k_bnapply<<<(NN*32+255)/256,256>>>(l);
    if (l < LL-1){
      k_vt<<<NB,128>>>(l);
      k_vnl1<<<NB,256>>>(vnW1, vnb1, l);
      k_vnbn1<<<1,256>>>(vnbn1g, vnbn1b, l);
      k_vnl2<<<NB,128>>>(vnW2, vnb2, l);
      k_vnbn2<<<1,128>>>(vnbn2g, vnbn2b, l);
    }
  }
  k_pool<<<NB,128>>>();
  k_head<<<NB,256>>>(headW, headb, headM, out);
}

// round 5
// speedup vs baseline: 2.1517x; 1.1864x over previous
#include <cuda_runtime.h>
#include <cuda_bf16.h>
#include <math.h>
#include <stdint.h>

#define NN 50000
#define NE 800000
#define FIN 64
#define HH 128
#define LL 3
#define CC 4
#define KK 32
#define NOPS 7
#define NB 512
#define NOUT 10
#define BNG 400

// ------------------------- device scratch (no allocs) -------------------------
__device__ float g_gr[(LL+1)*NN*HH];
__device__ float g_xw[NN*HH];
__device__ float g_sum[NN*HH];
__device__ float g_nrm[NN*HH];
__device__ float g_att[NN*HH];
__device__ float g_y[NN*HH];
__device__ float g_s0[NN];
__device__ float g_s1[NN];
__device__ float g_dinv[NN];
__device__ float g_minv[NN];
__device__ int   g_deg[NN];
__device__ int   g_rowptr[NN+1];
__device__ int   g_cursor[NN];
__device__ int   g_csrsrc[NE];
__device__ int   g_bstart[NB+1];
__device__ float g_wmix[LL*CC*NOPS];
__device__ float g_vn[NB*HH];
__device__ float g_vt[NB*HH];
__device__ float g_h1[NB*2*HH];
__device__ float g_h2[NB*HH];
__device__ float g_part[2*BNG*HH];
__device__ float g_scale[HH];
__device__ float g_shift[HH];
__device__ float g_pooled[NB*8*HH];
// W transposed to [outcol n=c*32+k][h], bf16 hi/lo split, per (l,o)
__device__ unsigned short g_Whi[LL*NOPS*16384];
__device__ unsigned short g_Wlo[LL*NOPS*16384];

// ------------------------- PTX helpers (baseline ISA, sm_80+) -------------------------
__device__ __forceinline__ uint32_t smem_u32(const void* p){
  uint32_t a; asm("{ .reg .u64 t; cvta.to.shared.u64 t, %1; cvt.u32.u64 %0, t; }" : "=r"(a) : "l"(p));
  return a;
}
__device__ __forceinline__ void ldsm4(uint32_t &r0, uint32_t &r1, uint32_t &r2, uint32_t &r3, uint32_t addr){
  asm volatile("ldmatrix.sync.aligned.m8n8.x4.shared.b16 {%0,%1,%2,%3}, [%4];"
    : "=r"(r0), "=r"(r1), "=r"(r2), "=r"(r3) : "r"(addr));
}
__device__ __forceinline__ void mma16816(float* d, const uint32_t* a, const uint32_t* b){
  asm volatile("mma.sync.aligned.m16n8k16.row.col.f32.bf16.bf16.f32 "
    "{%0,%1,%2,%3}, {%4,%5,%6,%7}, {%8,%9}, {%0,%1,%2,%3};"
    : "+f"(d[0]), "+f"(d[1]), "+f"(d[2]), "+f"(d[3])
    : "r"(a[0]), "r"(a[1]), "r"(a[2]), "r"(a[3]), "r"(b[0]), "r"(b[1]));
}

// ------------------------- CSR build -------------------------
__global__ void k_zero_deg(){
  int i = blockIdx.x*blockDim.x + threadIdx.x;
  if (i < NN) g_deg[i] = 0;
}
__global__ void k_count(const int* __restrict__ dst){
  int e = blockIdx.x*blockDim.x + threadIdx.x;
  if (e < NE) atomicAdd(&g_deg[dst[e]], 1);
}
// scan + nodeprep fused
__global__ void k_scan(){
  __shared__ int sm[1024];
  const int CH = (NN + 1023)/1024;
  int t = threadIdx.x;
  int s = 0;
  for (int i=0;i<CH;i++){ int idx = t*CH+i; if (idx<NN) s += g_deg[idx]; }
  sm[t] = s; __syncthreads();
  for (int off=1; off<1024; off<<=1){
    int v = (t>=off) ? sm[t-off] : 0;
    __syncthreads();
    if (t>=off) sm[t] += v;
    __syncthreads();
  }
  int run = (t>0)? sm[t-1] : 0;
  for (int i=0;i<CH;i++){
    int idx=t*CH+i;
    if (idx<NN){
      g_rowptr[idx]=run;
      g_cursor[idx]=run;
      int d = g_deg[idx];
      run += d;
      float dc = (float)max(d, 1);
      g_dinv[idx] = rsqrtf(dc);
      g_minv[idx] = 1.f/dc;
    }
  }
  if (t==1023) g_rowptr[NN] = sm[1023];
}
__global__ void k_scatter(const int* __restrict__ src, const int* __restrict__ dst){
  int e = blockIdx.x*blockDim.x + threadIdx.x;
  if (e < NE){
    int slot = atomicAdd(&g_cursor[dst[e]], 1);
    g_csrsrc[slot] = src[e];
  }
}
__global__ void k_bstart(const int* __restrict__ batch){
  int i = blockIdx.x*blockDim.x + threadIdx.x;
  if (i >= NN) return;
  int b = batch[i];
  if (i == 0){ for (int bb=0; bb<=b; bb++) g_bstart[bb] = 0; }
  else { int p = batch[i-1]; for (int bb=p+1; bb<=b; bb++) g_bstart[bb] = i; }
  if (i == NN-1){ for (int bb=b+1; bb<=NB; bb++) g_bstart[bb] = NN; }
}
__global__ void k_prepw(const float* __restrict__ alphas){
  int g = threadIdx.x;
  if (g < LL*CC){
    const float* a = alphas + g*NOPS;
    float mx = a[0];
    for (int o=1;o<NOPS;o++) mx = fmaxf(mx, a[o]);
    float e[NOPS]; float s = 0.f;
    for (int o=0;o<NOPS;o++){ e[o] = expf(a[o]-mx); s += e[o]; }
    for (int o=0;o<NOPS;o++) g_wmix[g*NOPS+o] = e[o]/s;
  }
}
__global__ void k_vninit(const float* __restrict__ vn0){
  int i = blockIdx.x*blockDim.x + threadIdx.x;
  if (i < NB*HH) g_vn[i] = vn0[i & (HH-1)];
}

// ------------------------- weight prep: transpose + bf16 split -------------------------
__global__ void k_wprep(const float* __restrict__ Wops){
  int idx = blockIdx.x*blockDim.x + threadIdx.x;
  if (idx >= LL*NOPS*16384) return;
  int lop = idx >> 14;
  int el  = idx & 16383;
  int l = lop / NOPS, o = lop % NOPS;
  int r = el >> 7;              // out col index n = c*32+k
  int h = el & 127;             // contraction dim
  int c = r >> 5, k = r & 31;
  float w = Wops[(((size_t)(l*CC + c)*NOPS + o)*HH + h)*KK + k];
  __nv_bfloat16 hb = __float2bfloat16(w);
  float res = w - __bfloat162float(hb);
  __nv_bfloat16 lb = __float2bfloat16(res);
  g_Whi[(size_t)lop*16384 + r*128 + h] = __bfloat16_as_ushort(hb);
  g_Wlo[(size_t)lop*16384 + r*128 + h] = __bfloat16_as_ushort(lb);
}

// ------------------------- lin1 + ELU -------------------------
__global__ void __launch_bounds__(128) k_lin1(const float* __restrict__ x,
    const float* __restrict__ W, const float* __restrict__ bias){
  __shared__ float Wt[HH*68];
  __shared__ float xs[16][FIN];
  int tid = threadIdx.x;
  for (int i=tid; i<FIN*HH; i+=128){ int h=i>>7, c=i&127; Wt[c*68+h] = W[i]; }
  int n0 = blockIdx.x*16;
  for (int i=tid; i<16*FIN; i+=128){
    int nl=i>>6, h=i&63; int n=n0+nl;
    xs[nl][h] = (n<NN)? x[n*FIN+h] : 0.f;
  }
  __syncthreads();
  float acc[16];
  float bv = bias[tid];
  #pragma unroll
  for (int nl=0;nl<16;nl++) acc[nl]=bv;
  #pragma unroll
  for (int h4=0; h4<FIN/4; h4++){
    float4 w4 = *(const float4*)&Wt[tid*68 + h4*4];
    #pragma unroll
    for (int nl=0;nl<16;nl++){
      float4 x4 = *(const float4*)&xs[nl][h4*4];
      acc[nl] += w4.x*x4.x + w4.y*x4.y + w4.z*x4.z + w4.w*x4.w;
    }
  }
  #pragma unroll
  for (int nl=0;nl<16;nl++){
    int n = n0+nl;
    if (n<NN){
      float a = acc[nl];
      a = a>0.f ? a : expm1f(a);
      g_gr[(size_t)n*HH+tid] = a;
    }
  }
}

// ------------------------- per-layer node prep -------------------------
__global__ void k_nodeA(const int* __restrict__ batch, const float* __restrict__ atta, int l){
  int w = (blockIdx.x*blockDim.x + threadIdx.x) >> 5;
  int lane = threadIdx.x & 31;
  if (w >= NN) return;
  int b = batch[w];
  float4 xv = ((const float4*)(g_gr + (size_t)l*NN*HH))[w*32 + lane];
  float4 vv = ((const float4*)g_vn)[b*32 + lane];
  xv.x += vv.x; xv.y += vv.y; xv.z += vv.z; xv.w += vv.w;
  ((float4*)g_xw)[w*32 + lane] = xv;
  float4 a0 = ((const float4*)(atta + l*2*HH))[lane];
  float4 a1 = ((const float4*)(atta + l*2*HH + HH))[lane];
  float s0 = xv.x*a0.x + xv.y*a0.y + xv.z*a0.z + xv.w*a0.w;
  float s1 = xv.x*a1.x + xv.y*a1.y + xv.z*a1.z + xv.w*a1.w;
  #pragma unroll
  for (int off=16; off; off>>=1){
    s0 += __shfl_xor_sync(0xffffffffu, s0, off);
    s1 += __shfl_xor_sync(0xffffffffu, s1, off);
  }
  if (lane==0){ g_s0[w]=s0; g_s1[w]=s1; }
}

// ------------------------- fused attention + aggregation (warp per node) -------------------------
__global__ void k_edge(){
  int w = (blockIdx.x*blockDim.x + threadIdx.x) >> 5;
  int lane = threadIdx.x & 31;
  if (w >= NN) return;
  int s = g_rowptr[w], e = g_rowptr[w+1];
  float s1v = g_s1[w];
  float dv = g_dinv[w];
  // pass 1: segment max over edges (lane-parallel)
  float m = -1e30f;
  for (int j=s+lane; j<e; j+=32){
    float ev = g_s0[g_csrsrc[j]] + s1v;
    ev = ev>0.f ? ev : 0.2f*ev;
    m = fmaxf(m, ev);
  }
  #pragma unroll
  for (int off=16; off; off>>=1) m = fmaxf(m, __shfl_xor_sync(0xffffffffu, m, off));
  if (e == s) m = 0.f;
  // pass 2: exp-sum
  float ss = 0.f;
  for (int j=s+lane; j<e; j+=32){
    float ev = g_s0[g_csrsrc[j]] + s1v;
    ev = ev>0.f ? ev : 0.2f*ev;
    ss += expf(ev - m);
  }
  #pragma unroll
  for (int off=16; off; off>>=1) ss += __shfl_xor_sync(0xffffffffu, ss, off);
  float sinv = 1.f/(ss + 1e-16f);
  // pass 3: whole-warp row gather with all three aggregations
  float4 a_s = make_float4(0.f,0.f,0.f,0.f);
  float4 a_n = a_s, a_a = a_s;
  for (int j=s; j<e; j++){
    int sn = g_csrsrc[j];
    float ev = g_s0[sn] + s1v;
    ev = ev>0.f ? ev : 0.2f*ev;
    float ca = expf(ev - m) * sinv;
    float nw = g_dinv[sn]*dv;
    float4 xv = ((const float4*)g_xw)[sn*32 + lane];
    a_s.x+=xv.x;      a_s.y+=xv.y;      a_s.z+=xv.z;      a_s.w+=xv.w;
    a_n.x+=nw*xv.x;   a_n.y+=nw*xv.y;   a_n.z+=nw*xv.z;   a_n.w+=nw*xv.w;
    a_a.x+=ca*xv.x;   a_a.y+=ca*xv.y;   a_a.z+=ca*xv.z;   a_a.w+=ca*xv.w;
  }
  ((float4*)g_sum)[w*32+lane]=a_s;
  ((float4*)g_nrm)[w*32+lane]=a_n;
  ((float4*)g_att)[w*32+lane]=a_a;
}

// ------------------------- warp-MMA mixed-op GEMM + LN + DARTS mix (v2) -------------------------
// block = 64 nodes x 128 outcols, K=128. 8 warps in 4x2 grid: warp = 16 rows x 64 cols.
// bf16 hi/lo split (3 products) into f32 accum. 2 CTAs/SM.
#define MT 64
#define PADK 136
#define SM_AHI 0
#define SM_ALO (MT*PADK*2)
#define SM_WHI (2*MT*PADK*2)
#define SM_WLO (SM_WHI + 128*PADK*2)
#define SM_BB  (SM_WLO + 128*PADK*2)
#define SM_LG  (SM_BB+512)
#define SM_LB  (SM_LG+512)
#define SMEM_MIX (SM_LB+512)

__constant__ int c_opseq[7] = {0,5,1,2,3,4,6};
__constant__ int c_asel[7]  = {0,0,1,2,3,4,5};

__global__ void __launch_bounds__(256,2) k_mix_mma(int l,
    const float* __restrict__ bops, const float* __restrict__ lng, const float* __restrict__ lnb){
  extern __shared__ char smc[];
  uint32_t sbase = smem_u32(smc);
  float* s_bb = (float*)(smc + SM_BB);
  float* s_lg = (float*)(smc + SM_LG);
  float* s_lb = (float*)(smc + SM_LB);
  int tid = threadIdx.x;
  int lane = tid & 31, w = tid >> 5;
  int wr = w & 3, wc = w >> 2;          // 4 row-groups x 2 col-groups
  int g = lane >> 2, tig = lane & 3;
  int n0 = blockIdx.x * MT;
  if (tid < 128){ s_lg[tid] = lng[l*128+tid]; s_lb[tid] = lnb[l*128+tid]; }

  // ldmatrix lane address offsets (bf16 elements)
  int a_off = ((lane&7) + ((lane>>3)&1)*8)*PADK + (lane>>4)*8;
  int b_off = (((lane>>4)&1)*8 + (lane&7))*PADK + ((lane>>3)&1)*8;
  uint32_t AbH = sbase + SM_AHI + (uint32_t)(wr*16*PADK + a_off)*2;
  uint32_t AbL = sbase + SM_ALO + (uint32_t)(wr*16*PADK + a_off)*2;
  uint32_t WbH = sbase + SM_WHI + (uint32_t)(wc*64*PADK)*2 + (uint32_t)b_off*2;
  uint32_t WbL = sbase + SM_WLO + (uint32_t)(wc*64*PADK)*2 + (uint32_t)b_off*2;

  float mix[8][4];
  #pragma unroll
  for (int f=0;f<8;f++){ mix[f][0]=0.f; mix[f][1]=0.f; mix[f][2]=0.f; mix[f][3]=0.f; }

  int prevA = -1;
  for (int oi=0; oi<7; oi++){
    int o = c_opseq[oi], asel = c_asel[oi];
    __syncthreads();
    if (asel != prevA){
      prevA = asel;
      #pragma unroll 1
      for (int it=0; it<16; it++){
        int wi = it*256 + tid;          // word index 0..4095
        int r = wi >> 6;
        int h0 = (wi & 63)*2;
        int n = n0 + r;
        float vx=0.f, vy=0.f;
        if (n < NN){
          size_t base = (size_t)n*HH + h0;
          if (asel==0){ float2 a = *(const float2*)(g_nrm+base); vx=a.x; vy=a.y; }
          else if (asel==1){ float2 a=*(const float2*)(g_xw+base); float2 bq=*(const float2*)(g_sum+base); vx=a.x+bq.x; vy=a.y+bq.y; }
          else if (asel==2){ float2 a=*(const float2*)(g_att+base); vx=a.x; vy=a.y; }
          else if (asel==3){ float2 a=*(const float2*)(g_xw+base); float2 bq=*(const float2*)(g_sum+base); float m=g_minv[n]; vx=a.x+bq.x*m; vy=a.y+bq.y*m; }
          else if (asel==4){ float2 bq=*(const float2*)(g_sum+base); float m=g_minv[n]; vx=bq.x*m; vy=bq.y*m; }
          else { float2 a=*(const float2*)(g_xw+base); vx=a.x; vy=a.y; }
        }
        __nv_bfloat16 hx = __float2bfloat16(vx);
        __nv_bfloat16 hy = __float2bfloat16(vy);
        __nv_bfloat16 lx = __float2bfloat16(vx - __bfloat162float(hx));
        __nv_bfloat16 ly = __float2bfloat16(vy - __bfloat162float(hy));
        uint32_t off = (uint32_t)(r*PADK + h0)*2;
        *(uint32_t*)(smc + SM_AHI + off) = (uint32_t)__bfloat16_as_ushort(hx) | ((uint32_t)__bfloat16_as_ushort(hy)<<16);
        *(uint32_t*)(smc + SM_ALO + off) = (uint32_t)__bfloat16_as_ushort(lx) | ((uint32_t)__bfloat16_as_ushort(ly)<<16);
      }
    }
    // W tiles -> smem (PADK padded)
    {
      const uint4* srcH = (const uint4*)(g_Whi + (size_t)(l*NOPS+o)*16384);
      const uint4* srcL = (const uint4*)(g_Wlo + (size_t)(l*NOPS+o)*16384);
      #pragma unroll
      for (int it=0; it<8; it++){
        int i = it*256 + tid;
        int row = i >> 4, q = i & 15;
        uint32_t off = (uint32_t)(row*PADK + q*8)*2;
        *(uint4*)(smc + SM_WHI + off) = srcH[i];
        *(uint4*)(smc + SM_WLO + off) = srcL[i];
      }
    }
    if (tid < 128){
      int c = tid>>5, k = tid&31;
      s_bb[tid] = bops[((size_t)(l*CC + c)*NOPS + o)*KK + k];
    }
    __syncthreads();

    float acc[8][4];
    #pragma unroll
    for (int f=0;f<8;f++){ acc[f][0]=0.f; acc[f][1]=0.f; acc[f][2]=0.f; acc[f][3]=0.f; }
    #pragma unroll 1
    for (int ks=0; ks<8; ks++){
      uint32_t k0b = (uint32_t)(ks*16)*2;
      uint32_t ah[4], al[4];
      ldsm4(ah[0],ah[1],ah[2],ah[3], AbH + k0b);
      ldsm4(al[0],al[1],al[2],al[3], AbL + k0b);
      #pragma unroll
      for (int nf=0; nf<4; nf++){
        uint32_t bh[4], bl[4];
        uint32_t woff = (uint32_t)(nf*16*PADK)*2 + k0b;
        ldsm4(bh[0],bh[1],bh[2],bh[3], WbH + woff);
        ldsm4(bl[0],bl[1],bl[2],bl[3], WbL + woff);
        mma16816(acc[2*nf],   ah, bh);
        mma16816(acc[2*nf],   ah, bl);
        mma16816(acc[2*nf],   al, bh);
        mma16816(acc[2*nf+1], ah, bh+2);
        mma16816(acc[2*nf+1], ah, bl+2);
        mma16816(acc[2*nf+1], al, bh+2);
      }
    }
    // epilogue: bias + LayerNorm(32) per (row, c) + affine + DARTS mix
    #pragma unroll
    for (int ch=0; ch<2; ch++){
      int c = wc*2 + ch;
      float tv[4][4];
      float sA=0.f, sqA=0.f, sB=0.f, sqB=0.f;
      #pragma unroll
      for (int fi=0; fi<4; fi++){
        int f = 4*ch + fi;
        int col0 = wc*64 + f*8 + 2*tig;
        float b0 = s_bb[col0], b1 = s_bb[col0+1];
        float t0 = acc[f][0]+b0, t1 = acc[f][1]+b1;
        float t2 = acc[f][2]+b0, t3 = acc[f][3]+b1;
        tv[fi][0]=t0; tv[fi][1]=t1; tv[fi][2]=t2; tv[fi][3]=t3;
        sA += t0+t1; sqA += t0*t0+t1*t1;
        sB += t2+t3; sqB += t2*t2+t3*t3;
      }
      sA += __shfl_xor_sync(0xffffffffu, sA, 1);  sqA += __shfl_xor_sync(0xffffffffu, sqA, 1);
      sB += __shfl_xor_sync(0xffffffffu, sB, 1);  sqB += __shfl_xor_sync(0xffffffffu, sqB, 1);
      sA += __shfl_xor_sync(0xffffffffu, sA, 2);  sqA += __shfl_xor_sync(0xffffffffu, sqA, 2);
      sB += __shfl_xor_sync(0xffffffffu, sB, 2);  sqB += __shfl_xor_sync(0xffffffffu, sqB, 2);
      float mA = sA*(1.f/32.f), vA = sqA*(1.f/32.f) - mA*mA;
      float mB = sB*(1.f/32.f), vB = sqB*(1.f/32.f) - mB*mB;
      float rA = rsqrtf(vA + 1e-5f), rB = rsqrtf(vB + 1e-5f);
      float wv = g_wmix[(l*CC + c)*NOPS + o];
      #pragma unroll
      for (int fi=0; fi<4; fi++){
        int f = 4*ch + fi;
        int col0 = wc*64 + f*8 + 2*tig;
        float lg0=s_lg[col0], lg1=s_lg[col0+1], lb0=s_lb[col0], lb1=s_lb[col0+1];
        mix[f][0] += wv*((tv[fi][0]-mA)*rA*lg0 + lb0);
        mix[f][1] += wv*((tv[fi][1]-mA)*rA*lg1 + lb1);
        mix[f][2] += wv*((tv[fi][2]-mB)*rB*lg0 + lb0);
        mix[f][3] += wv*((tv[fi][3]-mB)*rB*lg1 + lb1);
      }
    }
  }
  // write out
  int rA = n0 + wr*16 + g;
  int rB = rA + 8;
  #pragma unroll
  for (int f=0; f<8; f++){
    int col = wc*64 + f*8 + 2*tig;
    if (rA < NN) *(float2*)&g_y[(size_t)rA*HH + col] = make_float2(mix[f][0], mix[f][1]);
    if (rB < NN) *(float2*)&g_y[(size_t)rB*HH + col] = make_float2(mix[f][2], mix[f][3]);
  }
}

// ------------------------- BatchNorm over N (deterministic 2-stage) -------------------------
__global__ void k_bnstat(){
  int t = threadIdx.x; int b = blockIdx.x;
  float s=0.f, sq=0.f;
  for (int r=b; r<NN; r+=BNG){
    float v = g_y[(size_t)r*HH + t];
    s+=v; sq+=v*v;
  }
  g_part[b*HH+t]=s;
  g_part[BNG*HH + b*HH+t]=sq;
}
__global__ void k_bnfin(const float* __restrict__ bng, const float* __restrict__ bnb, int l){
  int t=threadIdx.x;
  float s=0.f, sq=0.f;
  for (int b=0;b<BNG;b++){ s+=g_part[b*HH+t]; sq+=g_part[BNG*HH+b*HH+t]; }
  float mean = s*(1.f/NN);
  float var  = sq*(1.f/NN) - mean*mean;
  float sc = bng[l*HH+t]*rsqrtf(var+1e-5f);
  g_scale[t]=sc;
  g_shift[t]=bnb[l*HH+t]-mean*sc;
}
__global__ void k_bnapply(int l){
  int i = blockIdx.x*blockDim.x+threadIdx.x;
  if (i < NN*32){
    float4 v = ((const float4*)g_y)[i];
    int cb = (i & 31)*4;
    v.x = v.x*g_scale[cb+0]+g_shift[cb+0];
    v.y = v.y*g_scale[cb+1]+g_shift[cb+1];
    v.z = v.z*g_scale[cb+2]+g_shift[cb+2];
    v.w = v.w*g_scale[cb+3]+g_shift[cb+3];
    ((float4*)(g_gr + (size_t)(l+1)*NN*HH))[i] = v;
  }
}

// ------------------------- virtual node MLP -------------------------
__global__ void k_vt(int l){
  int b=blockIdx.x, t=threadIdx.x;
  int s=g_bstart[b], e=g_bstart[b+1];
  float acc=0.f;
  const float* gp = g_gr + (size_t)(l+1)*NN*HH;
  for (int r=s;r<e;r++) acc += gp[(size_t)r*HH+t];
  g_vt[b*HH+t] = acc + g_vn[b*HH+t];
}
__global__ void k_vnl1(const float* __restrict__ W1, const float* __restrict__ b1, int l){
  __shared__ float vr[HH];
  int row=blockIdx.x, t=threadIdx.x;
  if (t<HH) vr[t]=g_vt[row*HH+t];
  __syncthreads();
  float acc = b1[l*2*HH+t];
  const float* w = W1 + (size_t)l*HH*2*HH + t;
  #pragma unroll 4
  for (int h=0;h<HH;h++) acc += vr[h]*w[h*2*HH];
  g_h1[row*2*HH+t]=acc;
}
__global__ void k_vnbn1(const float* __restrict__ g, const float* __restrict__ bb, int l){
  int t=threadIdx.x;
  float s=0.f, sq=0.f;
  for (int r=0;r<NB;r++){ float v=g_h1[r*2*HH+t]; s+=v; sq+=v*v; }
  float mean=s*(1.f/NB);
  float var=sq*(1.f/NB)-mean*mean;
  float rs=rsqrtf(var+1e-5f);
  float gam=g[l*2*HH+t], bet=bb[l*2*HH+t];
  for (int r=0;r<NB;r++){
    float v=g_h1[r*2*HH+t];
    v=(v-mean)*rs*gam+bet;
    g_h1[r*2*HH+t] = v>0.f? v:0.f;
  }
}
__global__ void k_vnl2(const float* __restrict__ W2, const float* __restrict__ b2, int l){
  __shared__ float hr[2*HH];
  int row=blockIdx.x, t=threadIdx.x;
  hr[t]=g_h1[row*2*HH+t];
  hr[t+HH]=g_h1[row*2*HH+t+HH];
  __syncthreads();
  float acc = b2[l*HH+t];
  const float* w = W2 + (size_t)l*2*HH*HH + t;
  #pragma unroll 4
  for (int h=0;h<2*HH;h++) acc += hr[h]*w[h*HH];
  g_h2[row*HH+t]=acc;
}
__global__ void k_vnbn2(const float* __restrict__ g, const float* __restrict__ bb, int l){
  int t=threadIdx.x;
  float s=0.f, sq=0.f;
  for (int r=0;r<NB;r++){ float v=g_h2[r*HH+t]; s+=v; sq+=v*v; }
  float mean=s*(1.f/NB);
  float var=sq*(1.f/NB)-mean*mean;
  float rs=rsqrtf(var+1e-5f);
  float gam=g[l*HH+t], bet=bb[l*HH+t];
  for (int r=0;r<NB;r++){
    float v=g_h2[r*HH+t];
    v=(v-mean)*rs*gam+bet;
    g_vn[r*HH+t] = v>0.f? v:0.f;
  }
}

// ------------------------- pooling + head -------------------------
__global__ void k_pool(){
  int b=blockIdx.x, t=threadIdx.x;
  int s=g_bstart[b], e=g_bstart[b+1];
  float inv = 1.f/(float)max(e-s,1);
  for (int st=0; st<4; st++){
    const float* gp = g_gr + (size_t)st*NN*HH;
    float sum=0.f, mx=-1e30f;
    for (int r=s;r<e;r++){ float v=gp[(size_t)r*HH+t]; sum+=v; mx=fmaxf(mx,v); }
    if (e==s) mx=0.f;
    g_pooled[b*1024 + st*HH + t] = sum*inv;
    g_pooled[b*1024 + 512 + st*HH + t] = mx;
  }
}
__global__ void k_head(const float* __restrict__ hW, const float* __restrict__ hb,
                       const float* __restrict__ hM, float* __restrict__ out){
  __shared__ float red[NOUT];
  int b=blockIdx.x, t=threadIdx.x;
  if (t<NOUT) red[t]=0.f;
  __syncthreads();
  float acc[NOUT];
  #pragma unroll
  for (int j=0;j<NOUT;j++) acc[j]=0.f;
  for (int d=t; d<1024; d+=256){
    float pv = g_pooled[b*1024+d];
    const float* wrow = hW + d*NOUT;
    const float* mrow = hM + d*NOUT;
    #pragma unroll
    for (int j=0;j<NOUT;j++) acc[j] += pv*wrow[j]*mrow[j];
  }
  #pragma unroll
  for (int j=0;j<NOUT;j++) atomicAdd(&red[j], acc[j]);
  __syncthreads();
  if (t<NOUT) out[b*NOUT+t] = red[t] + hb[t];
}

// ------------------------- launch -------------------------
extern "C" void kernel_launch(void* const* d_in, const int* in_sizes, int n_in,
                              void* d_out, int out_size){
  const float* x      = (const float*)d_in[0];
  const int*   ei     = (const int*)d_in[1];
  const int*   batch  = (const int*)d_in[2];
  const float* lin1W  = (const float*)d_in[3];
  const float* lin1b  = (const float*)d_in[4];
  const float* vn0    = (const float*)d_in[5];
  const float* Wops   = (const float*)d_in[6];
  const float* bops   = (const float*)d_in[7];
  const float* atta   = (const float*)d_in[8];
  const float* lng    = (const float*)d_in[9];
  const float* lnb    = (const float*)d_in[10];
  const float* bng    = (const float*)d_in[11];
  const float* bnb    = (const float*)d_in[12];
  const float* vnW1   = (const float*)d_in[13];
  const float* vnb1   = (const float*)d_in[14];
  const float* vnbn1g = (const float*)d_in[15];
  const float* vnbn1b = (const float*)d_in[16];
  const float* vnW2   = (const float*)d_in[17];
  const float* vnb2   = (const float*)d_in[18];
  const float* vnbn2g = (const float*)d_in[19];
  const float* vnbn2b = (const float*)d_in[20];
  const float* alphas = (const float*)d_in[21];
  const float* headW  = (const float*)d_in[22];
  const float* headb  = (const float*)d_in[23];
  const float* headM  = (const float*)d_in[24];
  float* out = (float*)d_out;
  const int* src = ei;
  const int* dst = ei + NE;

  cudaFuncSetAttribute(k_mix_mma, cudaFuncAttributeMaxDynamicSharedMemorySize, SMEM_MIX);

  const int NBLK = (NN + 255)/256;
  const int WBLK = (NN*32 + 255)/256;
  const int EBLK = (NE + 255)/256;
  const int MIXBLK = (NN + MT-1)/MT;   // 782

  k_zero_deg<<<NBLK,256>>>();
  k_count<<<EBLK,256>>>(dst);
  k_scan<<<1,1024>>>();
  k_lin1<<<(NN+15)/16,128>>>(x, lin1W, lin1b);
  k_scatter<<<EBLK,256>>>(src, dst);
  k_bstart<<<NBLK,256>>>(batch);
  k_prepw<<<1,32>>>(alphas);
  k_vninit<<<(NB*HH+255)/256,256>>>(vn0);
  k_wprep<<<(LL*NOPS*16384+255)/256,256>>>(Wops);

  for (int l=0; l<LL; l++){
    k_nodeA<<<WBLK,256>>>(batch, atta, l);
    k_edge<<<WBLK,256>>>();
    k_mix_mma<<<MIXBLK,256,SMEM_MIX>>>(l, bops, lng, lnb);
    k_bnstat<<<BNG,128>>>();
    k_bnfin<<<1,128>>>(bng, bnb, l);
    k_bnapply<<<(NN*32+255)/256,256>>>(l);
    if (l < LL-1){
      k_vt<<<NB,128>>>(l);
      k_vnl1<<<NB,256>>>(vnW1, vnb1, l);
      k_vnbn1<<<1,256>>>(vnbn1g, vnbn1b, l);
      k_vnl2<<<NB,128>>>(vnW2, vnb2, l);
      k_vnbn2<<<1,128>>>(vnbn2g, vnbn2b, l);
    }
  }
  k_pool<<<NB,128>>>();
  k_head<<<NB,256>>>(headW, headb, headM, out);
}

// round 6
// speedup vs baseline: 2.5202x; 1.1713x over previous
#include <cuda_runtime.h>
#include <cuda_bf16.h>
#include <math.h>
#include <stdint.h>

#define NN 50000
#define NE 800000
#define FIN 64
#define HH 128
#define LL 3
#define CC 4
#define KK 32
#define NOPS 7
#define NB 512
#define NOUT 10
#define BNG 400

// ------------------------- device scratch (no allocs) -------------------------
__device__ float g_gr[(LL+1)*NN*HH];
__device__ float g_xw[NN*HH];
__device__ float g_sum[NN*HH];
__device__ float g_nrm[NN*HH];
__device__ float g_att[NN*HH];
__device__ float g_y[NN*HH];
__device__ float g_s0[NN];
__device__ float g_s1[NN];
__device__ float g_dinv[NN];
__device__ float g_minv[NN];
__device__ int   g_deg[NN];
__device__ int   g_rowptr[NN+1];
__device__ int   g_cursor[NN];
__device__ int   g_csrsrc[NE];
__device__ int   g_bstart[NB+1];
__device__ float g_wmix[LL*CC*NOPS];
__device__ float g_vn[NB*HH];
__device__ float g_vt[NB*HH];
__device__ float g_h1[NB*2*HH];
__device__ float g_h2[NB*HH];
__device__ float g_part[2*BNG*HH];
__device__ float g_scale[HH];
__device__ float g_shift[HH];
__device__ float g_sc1[2*HH];
__device__ float g_sh1[2*HH];
__device__ float g_sc2[HH];
__device__ float g_sh2[HH];
__device__ float g_pooled[NB*8*HH];
__device__ int   g_cbn = 0;
__device__ int   g_c1 = 0;
__device__ int   g_c2 = 0;
// W transposed to [outcol n=c*32+k][h], bf16 hi/lo split, per (l,o)
__device__ unsigned short g_Whi[LL*NOPS*16384];
__device__ unsigned short g_Wlo[LL*NOPS*16384];
// lin1 weights transposed [outcol r=0..127][h=0..63], bf16 split
__device__ unsigned short g_W1hi[128*64];
__device__ unsigned short g_W1lo[128*64];

// ------------------------- PTX helpers (baseline ISA, sm_80+) -------------------------
__device__ __forceinline__ uint32_t smem_u32(const void* p){
  uint32_t a; asm("{ .reg .u64 t; cvta.to.shared.u64 t, %1; cvt.u32.u64 %0, t; }" : "=r"(a) : "l"(p));
  return a;
}
__device__ __forceinline__ void ldsm4(uint32_t &r0, uint32_t &r1, uint32_t &r2, uint32_t &r3, uint32_t addr){
  asm volatile("ldmatrix.sync.aligned.m8n8.x4.shared.b16 {%0,%1,%2,%3}, [%4];"
    : "=r"(r0), "=r"(r1), "=r"(r2), "=r"(r3) : "r"(addr));
}
__device__ __forceinline__ void mma16816(float* d, const uint32_t* a, const uint32_t* b){
  asm volatile("mma.sync.aligned.m16n8k16.row.col.f32.bf16.bf16.f32 "
    "{%0,%1,%2,%3}, {%4,%5,%6,%7}, {%8,%9}, {%0,%1,%2,%3};"
    : "+f"(d[0]), "+f"(d[1]), "+f"(d[2]), "+f"(d[3])
    : "r"(a[0]), "r"(a[1]), "r"(a[2]), "r"(a[3]), "r"(b[0]), "r"(b[1]));
}

// ------------------------- CSR build -------------------------
__global__ void k_zero_deg(){
  int i = blockIdx.x*blockDim.x + threadIdx.x;
  if (i < NN) g_deg[i] = 0;
}
__global__ void k_count(const int* __restrict__ dst){
  int e = blockIdx.x*blockDim.x + threadIdx.x;
  if (e < NE) atomicAdd(&g_deg[dst[e]], 1);
}
// scan + nodeprep fused
__global__ void k_scan(){
  __shared__ int sm[1024];
  const int CH = (NN + 1023)/1024;
  int t = threadIdx.x;
  int s = 0;
  for (int i=0;i<CH;i++){ int idx = t*CH+i; if (idx<NN) s += g_deg[idx]; }
  sm[t] = s; __syncthreads();
  for (int off=1; off<1024; off<<=1){
    int v = (t>=off) ? sm[t-off] : 0;
    __syncthreads();
    if (t>=off) sm[t] += v;
    __syncthreads();
  }
  int run = (t>0)? sm[t-1] : 0;
  for (int i=0;i<CH;i++){
    int idx=t*CH+i;
    if (idx<NN){
      g_rowptr[idx]=run;
      g_cursor[idx]=run;
      int d = g_deg[idx];
      run += d;
      float dc = (float)max(d, 1);
      g_dinv[idx] = rsqrtf(dc);
      g_minv[idx] = 1.f/dc;
    }
  }
  if (t==1023) g_rowptr[NN] = sm[1023];
}
__global__ void k_scatter(const int* __restrict__ src, const int* __restrict__ dst){
  int e = blockIdx.x*blockDim.x + threadIdx.x;
  if (e < NE){
    int slot = atomicAdd(&g_cursor[dst[e]], 1);
    g_csrsrc[slot] = src[e];
  }
}
__global__ void k_bstart(const int* __restrict__ batch){
  int i = blockIdx.x*blockDim.x + threadIdx.x;
  if (i >= NN) return;
  int b = batch[i];
  if (i == 0){ for (int bb=0; bb<=b; bb++) g_bstart[bb] = 0; }
  else { int p = batch[i-1]; for (int bb=p+1; bb<=b; bb++) g_bstart[bb] = i; }
  if (i == NN-1){ for (int bb=b+1; bb<=NB; bb++) g_bstart[bb] = NN; }
}
__global__ void k_prepw(const float* __restrict__ alphas){
  int g = threadIdx.x;
  if (g < LL*CC){
    const float* a = alphas + g*NOPS;
    float mx = a[0];
    for (int o=1;o<NOPS;o++) mx = fmaxf(mx, a[o]);
    float e[NOPS]; float s = 0.f;
    for (int o=0;o<NOPS;o++){ e[o] = expf(a[o]-mx); s += e[o]; }
    for (int o=0;o<NOPS;o++) g_wmix[g*NOPS+o] = e[o]/s;
  }
}
__global__ void k_vninit(const float* __restrict__ vn0){
  int i = blockIdx.x*blockDim.x + threadIdx.x;
  if (i < NB*HH) g_vn[i] = vn0[i & (HH-1)];
}

// ------------------------- weight prep -------------------------
__global__ void k_wprep(const float* __restrict__ Wops){
  int idx = blockIdx.x*blockDim.x + threadIdx.x;
  if (idx >= LL*NOPS*16384) return;
  int lop = idx >> 14;
  int el  = idx & 16383;
  int l = lop / NOPS, o = lop % NOPS;
  int r = el >> 7;              // out col index n = c*32+k
  int h = el & 127;             // contraction dim
  int c = r >> 5, k = r & 31;
  float w = Wops[(((size_t)(l*CC + c)*NOPS + o)*HH + h)*KK + k];
  __nv_bfloat16 hb = __float2bfloat16(w);
  float res = w - __bfloat162float(hb);
  __nv_bfloat16 lb = __float2bfloat16(res);
  g_Whi[(size_t)lop*16384 + r*128 + h] = __bfloat16_as_ushort(hb);
  g_Wlo[(size_t)lop*16384 + r*128 + h] = __bfloat16_as_ushort(lb);
}
__global__ void k_wprep1(const float* __restrict__ W){
  int idx = blockIdx.x*blockDim.x + threadIdx.x;
  if (idx >= 128*64) return;
  int r = idx >> 6, h = idx & 63;
  float w = W[h*128 + r];
  __nv_bfloat16 hb = __float2bfloat16(w);
  float res = w - __bfloat162float(hb);
  __nv_bfloat16 lb = __float2bfloat16(res);
  g_W1hi[r*64+h] = __bfloat16_as_ushort(hb);
  g_W1lo[r*64+h] = __bfloat16_as_ushort(lb);
}

// ------------------------- lin1 + ELU via warp MMA -------------------------
#define PADK1 72
#define L1_AHI 0
#define L1_ALO (64*PADK1*2)
#define L1_WHI (2*64*PADK1*2)
#define L1_WLO (L1_WHI + 128*PADK1*2)
#define L1_BB  (L1_WLO + 128*PADK1*2)
#define SMEM_L1 (L1_BB + 512)

__global__ void __launch_bounds__(256,3) k_lin1_mma(const float* __restrict__ x,
    const float* __restrict__ bias){
  extern __shared__ char smc[];
  uint32_t sbase = smem_u32(smc);
  float* s_b1 = (float*)(smc + L1_BB);
  int tid = threadIdx.x;
  int lane = tid & 31, w = tid >> 5;
  int wr = w & 3, wc = w >> 2;
  int g = lane >> 2, tig = lane & 3;
  int n0 = blockIdx.x * 64;
  if (tid < 128) s_b1[tid] = bias[tid];

  // A build: 64 nodes x 64 feat, bf16 split
  #pragma unroll 1
  for (int it=0; it<8; it++){
    int wi = it*256 + tid;            // 0..2047
    int r = wi >> 5;
    int h0 = (wi & 31)*2;
    int n = n0 + r;
    float vx=0.f, vy=0.f;
    if (n < NN){
      float2 a = *(const float2*)(x + (size_t)n*FIN + h0);
      vx=a.x; vy=a.y;
    }
    __nv_bfloat16 hx = __float2bfloat16(vx);
    __nv_bfloat16 hy = __float2bfloat16(vy);
    __nv_bfloat16 lx = __float2bfloat16(vx - __bfloat162float(hx));
    __nv_bfloat16 ly = __float2bfloat16(vy - __bfloat162float(hy));
    uint32_t off = (uint32_t)(r*PADK1 + h0)*2;
    *(uint32_t*)(smc + L1_AHI + off) = (uint32_t)__bfloat16_as_ushort(hx) | ((uint32_t)__bfloat16_as_ushort(hy)<<16);
    *(uint32_t*)(smc + L1_ALO + off) = (uint32_t)__bfloat16_as_ushort(lx) | ((uint32_t)__bfloat16_as_ushort(ly)<<16);
  }
  // W load: 128 x 64
  {
    const uint4* srcH = (const uint4*)g_W1hi;
    const uint4* srcL = (const uint4*)g_W1lo;
    #pragma unroll
    for (int it=0; it<4; it++){
      int i = it*256 + tid;           // 0..1023
      int row = i >> 3, q = i & 7;
      uint32_t off = (uint32_t)(row*PADK1 + q*8)*2;
      *(uint4*)(smc + L1_WHI + off) = srcH[i];
      *(uint4*)(smc + L1_WLO + off) = srcL[i];
    }
  }
  __syncthreads();

  int a_off = ((lane&7) + ((lane>>3)&1)*8)*PADK1 + (lane>>4)*8;
  int b_off = (((lane>>4)&1)*8 + (lane&7))*PADK1 + ((lane>>3)&1)*8;
  uint32_t AbH = sbase + L1_AHI + (uint32_t)(wr*16*PADK1 + a_off)*2;
  uint32_t AbL = sbase + L1_ALO + (uint32_t)(wr*16*PADK1 + a_off)*2;
  uint32_t WbH = sbase + L1_WHI + (uint32_t)(wc*64*PADK1 + b_off)*2;
  uint32_t WbL = sbase + L1_WLO + (uint32_t)(wc*64*PADK1 + b_off)*2;

  float acc[8][4];
  #pragma unroll
  for (int f=0;f<8;f++){ acc[f][0]=0.f; acc[f][1]=0.f; acc[f][2]=0.f; acc[f][3]=0.f; }
  #pragma unroll
  for (int ks=0; ks<4; ks++){
    uint32_t k0b = (uint32_t)(ks*16)*2;
    uint32_t ah[4], al[4];
    ldsm4(ah[0],ah[1],ah[2],ah[3], AbH + k0b);
    ldsm4(al[0],al[1],al[2],al[3], AbL + k0b);
    #pragma unroll
    for (int nf=0; nf<4; nf++){
      uint32_t bh[4], bl[4];
      uint32_t woff = (uint32_t)(nf*16*PADK1)*2 + k0b;
      ldsm4(bh[0],bh[1],bh[2],bh[3], WbH + woff);
      ldsm4(bl[0],bl[1],bl[2],bl[3], WbL + woff);
      mma16816(acc[2*nf],   ah, bh);
      mma16816(acc[2*nf],   ah, bl);
      mma16816(acc[2*nf],   al, bh);
      mma16816(acc[2*nf+1], ah, bh+2);
      mma16816(acc[2*nf+1], ah, bl+2);
      mma16816(acc[2*nf+1], al, bh+2);
    }
  }
  int rA = n0 + wr*16 + g;
  int rB = rA + 8;
  #pragma unroll
  for (int f=0; f<8; f++){
    int col = wc*64 + f*8 + 2*tig;
    float b0 = s_b1[col], b1 = s_b1[col+1];
    float t0 = acc[f][0]+b0, t1 = acc[f][1]+b1;
    float t2 = acc[f][2]+b0, t3 = acc[f][3]+b1;
    t0 = t0>0.f ? t0 : expm1f(t0);
    t1 = t1>0.f ? t1 : expm1f(t1);
    t2 = t2>0.f ? t2 : expm1f(t2);
    t3 = t3>0.f ? t3 : expm1f(t3);
    if (rA < NN) *(float2*)&g_gr[(size_t)rA*HH + col] = make_float2(t0, t1);
    if (rB < NN) *(float2*)&g_gr[(size_t)rB*HH + col] = make_float2(t2, t3);
  }
}

// ------------------------- per-layer node prep -------------------------
__global__ void k_nodeA(const int* __restrict__ batch, const float* __restrict__ atta, int l){
  int w = (blockIdx.x*blockDim.x + threadIdx.x) >> 5;
  int lane = threadIdx.x & 31;
  if (w >= NN) return;
  int b = batch[w];
  float4 xv = ((const float4*)(g_gr + (size_t)l*NN*HH))[w*32 + lane];
  float4 vv = ((const float4*)g_vn)[b*32 + lane];
  xv.x += vv.x; xv.y += vv.y; xv.z += vv.z; xv.w += vv.w;
  ((float4*)g_xw)[w*32 + lane] = xv;
  float4 a0 = ((const float4*)(atta + l*2*HH))[lane];
  float4 a1 = ((const float4*)(atta + l*2*HH + HH))[lane];
  float s0 = xv.x*a0.x + xv.y*a0.y + xv.z*a0.z + xv.w*a0.w;
  float s1 = xv.x*a1.x + xv.y*a1.y + xv.z*a1.z + xv.w*a1.w;
  #pragma unroll
  for (int off=16; off; off>>=1){
    s0 += __shfl_xor_sync(0xffffffffu, s0, off);
    s1 += __shfl_xor_sync(0xffffffffu, s1, off);
  }
  if (lane==0){ g_s0[w]=s0; g_s1[w]=s1; }
}

// ------------------------- fused attention + aggregation (warp per node) -------------------------
__global__ void k_edge(){
  int w = (blockIdx.x*blockDim.x + threadIdx.x) >> 5;
  int lane = threadIdx.x & 31;
  if (w >= NN) return;
  int s = g_rowptr[w], e = g_rowptr[w+1];
  float s1v = g_s1[w];
  float dv = g_dinv[w];
  float m = -1e30f;
  for (int j=s+lane; j<e; j+=32){
    float ev = g_s0[g_csrsrc[j]] + s1v;
    ev = ev>0.f ? ev : 0.2f*ev;
    m = fmaxf(m, ev);
  }
  #pragma unroll
  for (int off=16; off; off>>=1) m = fmaxf(m, __shfl_xor_sync(0xffffffffu, m, off));
  if (e == s) m = 0.f;
  float ss = 0.f;
  for (int j=s+lane; j<e; j+=32){
    float ev = g_s0[g_csrsrc[j]] + s1v;
    ev = ev>0.f ? ev : 0.2f*ev;
    ss += expf(ev - m);
  }
  #pragma unroll
  for (int off=16; off; off>>=1) ss += __shfl_xor_sync(0xffffffffu, ss, off);
  float sinv = 1.f/(ss + 1e-16f);
  float4 a_s = make_float4(0.f,0.f,0.f,0.f);
  float4 a_n = a_s, a_a = a_s;
  for (int j=s; j<e; j++){
    int sn = g_csrsrc[j];
    float ev = g_s0[sn] + s1v;
    ev = ev>0.f ? ev : 0.2f*ev;
    float ca = expf(ev - m) * sinv;
    float nw = g_dinv[sn]*dv;
    float4 xv = ((const float4*)g_xw)[sn*32 + lane];
    a_s.x+=xv.x;      a_s.y+=xv.y;      a_s.z+=xv.z;      a_s.w+=xv.w;
    a_n.x+=nw*xv.x;   a_n.y+=nw*xv.y;   a_n.z+=nw*xv.z;   a_n.w+=nw*xv.w;
    a_a.x+=ca*xv.x;   a_a.y+=ca*xv.y;   a_a.z+=ca*xv.z;   a_a.w+=ca*xv.w;
  }
  ((float4*)g_sum)[w*32+lane]=a_s;
  ((float4*)g_nrm)[w*32+lane]=a_n;
  ((float4*)g_att)[w*32+lane]=a_a;
}

// ------------------------- warp-MMA mixed-op GEMM + LN + DARTS mix -------------------------
#define MT 64
#define PADK 136
#define SM_AHI 0
#define SM_ALO (MT*PADK*2)
#define SM_WHI (2*MT*PADK*2)
#define SM_WLO (SM_WHI + 128*PADK*2)
#define SM_BB  (SM_WLO + 128*PADK*2)
#define SM_LG  (SM_BB+512)
#define SM_LB  (SM_LG+512)
#define SMEM_MIX (SM_LB+512)

__constant__ int c_opseq[7] = {0,5,1,2,3,4,6};
__constant__ int c_asel[7]  = {0,0,1,2,3,4,5};

__global__ void __launch_bounds__(256,2) k_mix_mma(int l,
    const float* __restrict__ bops, const float* __restrict__ lng, const float* __restrict__ lnb){
  extern __shared__ char smc[];
  uint32_t sbase = smem_u32(smc);
  float* s_bb = (float*)(smc + SM_BB);
  float* s_lg = (float*)(smc + SM_LG);
  float* s_lb = (float*)(smc + SM_LB);
  int tid = threadIdx.x;
  int lane = tid & 31, w = tid >> 5;
  int wr = w & 3, wc = w >> 2;
  int g = lane >> 2, tig = lane & 3;
  int n0 = blockIdx.x * MT;
  if (tid < 128){ s_lg[tid] = lng[l*128+tid]; s_lb[tid] = lnb[l*128+tid]; }

  int a_off = ((lane&7) + ((lane>>3)&1)*8)*PADK + (lane>>4)*8;
  int b_off = (((lane>>4)&1)*8 + (lane&7))*PADK + ((lane>>3)&1)*8;
  uint32_t AbH = sbase + SM_AHI + (uint32_t)(wr*16*PADK + a_off)*2;
  uint32_t AbL = sbase + SM_ALO + (uint32_t)(wr*16*PADK + a_off)*2;
  uint32_t WbH = sbase + SM_WHI + (uint32_t)(wc*64*PADK)*2 + (uint32_t)b_off*2;
  uint32_t WbL = sbase + SM_WLO + (uint32_t)(wc*64*PADK)*2 + (uint32_t)b_off*2;

  float mix[8][4];
  #pragma unroll
  for (int f=0;f<8;f++){ mix[f][0]=0.f; mix[f][1]=0.f; mix[f][2]=0.f; mix[f][3]=0.f; }

  int prevA = -1;
  for (int oi=0; oi<7; oi++){
    int o = c_opseq[oi], asel = c_asel[oi];
    __syncthreads();
    if (asel != prevA){
      prevA = asel;
      #pragma unroll 1
      for (int it=0; it<16; it++){
        int wi = it*256 + tid;
        int r = wi >> 6;
        int h0 = (wi & 63)*2;
        int n = n0 + r;
        float vx=0.f, vy=0.f;
        if (n < NN){
          size_t base = (size_t)n*HH + h0;
          if (asel==0){ float2 a = *(const float2*)(g_nrm+base); vx=a.x; vy=a.y; }
          else if (asel==1){ float2 a=*(const float2*)(g_xw+base); float2 bq=*(const float2*)(g_sum+base); vx=a.x+bq.x; vy=a.y+bq.y; }
          else if (asel==2){ float2 a=*(const float2*)(g_att+base); vx=a.x; vy=a.y; }
          else if (asel==3){ float2 a=*(const float2*)(g_xw+base); float2 bq=*(const float2*)(g_sum+base); float m=g_minv[n]; vx=a.x+bq.x*m; vy=a.y+bq.y*m; }
          else if (asel==4){ float2 bq=*(const float2*)(g_sum+base); float m=g_minv[n]; vx=bq.x*m; vy=bq.y*m; }
          else { float2 a=*(const float2*)(g_xw+base); vx=a.x; vy=a.y; }
        }
        __nv_bfloat16 hx = __float2bfloat16(vx);
        __nv_bfloat16 hy = __float2bfloat16(vy);
        __nv_bfloat16 lx = __float2bfloat16(vx - __bfloat162float(hx));
        __nv_bfloat16 ly = __float2bfloat16(vy - __bfloat162float(hy));
        uint32_t off = (uint32_t)(r*PADK + h0)*2;
        *(uint32_t*)(smc + SM_AHI + off) = (uint32_t)__bfloat16_as_ushort(hx) | ((uint32_t)__bfloat16_as_ushort(hy)<<16);
        *(uint32_t*)(smc + SM_ALO + off) = (uint32_t)__bfloat16_as_ushort(lx) | ((uint32_t)__bfloat16_as_ushort(ly)<<16);
      }
    }
    {
      const uint4* srcH = (const uint4*)(g_Whi + (size_t)(l*NOPS+o)*16384);
      const uint4* srcL = (const uint4*)(g_Wlo + (size_t)(l*NOPS+o)*16384);
      #pragma unroll
      for (int it=0; it<8; it++){
        int i = it*256 + tid;
        int row = i >> 4, q = i & 15;
        uint32_t off = (uint32_t)(row*PADK + q*8)*2;
        *(uint4*)(smc + SM_WHI + off) = srcH[i];
        *(uint4*)(smc + SM_WLO + off) = srcL[i];
      }
    }
    if (tid < 128){
      int c = tid>>5, k = tid&31;
      s_bb[tid] = bops[((size_t)(l*CC + c)*NOPS + o)*KK + k];
    }
    __syncthreads();

    float acc[8][4];
    #pragma unroll
    for (int f=0;f<8;f++){ acc[f][0]=0.f; acc[f][1]=0.f; acc[f][2]=0.f; acc[f][3]=0.f; }
    #pragma unroll 1
    for (int ks=0; ks<8; ks++){
      uint32_t k0b = (uint32_t)(ks*16)*2;
      uint32_t ah[4], al[4];
      ldsm4(ah[0],ah[1],ah[2],ah[3], AbH + k0b);
      ldsm4(al[0],al[1],al[2],al[3], AbL + k0b);
      #pragma unroll
      for (int nf=0; nf<4; nf++){
        uint32_t bh[4], bl[4];
        uint32_t woff = (uint32_t)(nf*16*PADK)*2 + k0b;
        ldsm4(bh[0],bh[1],bh[2],bh[3], WbH + woff);
        ldsm4(bl[0],bl[1],bl[2],bl[3], WbL + woff);
        mma16816(acc[2*nf],   ah, bh);
        mma16816(acc[2*nf],   ah, bl);
        mma16816(acc[2*nf],   al, bh);
        mma16816(acc[2*nf+1], ah, bh+2);
        mma16816(acc[2*nf+1], ah, bl+2);
        mma16816(acc[2*nf+1], al, bh+2);
      }
    }
    #pragma unroll
    for (int ch=0; ch<2; ch++){
      int c = wc*2 + ch;
      float tv[4][4];
      float sA=0.f, sqA=0.f, sB=0.f, sqB=0.f;
      #pragma unroll
      for (int fi=0; fi<4; fi++){
        int f = 4*ch + fi;
        int col0 = wc*64 + f*8 + 2*tig;
        float b0 = s_bb[col0], b1 = s_bb[col0+1];
        float t0 = acc[f][0]+b0, t1 = acc[f][1]+b1;
        float t2 = acc[f][2]+b0, t3 = acc[f][3]+b1;
        tv[fi][0]=t0; tv[fi][1]=t1; tv[fi][2]=t2; tv[fi][3]=t3;
        sA += t0+t1; sqA += t0*t0+t1*t1;
        sB += t2+t3; sqB += t2*t2+t3*t3;
      }
      sA += __shfl_xor_sync(0xffffffffu, sA, 1);  sqA += __shfl_xor_sync(0xffffffffu, sqA, 1);
      sB += __shfl_xor_sync(0xffffffffu, sB, 1);  sqB += __shfl_xor_sync(0xffffffffu, sqB, 1);
      sA += __shfl_xor_sync(0xffffffffu, sA, 2);  sqA += __shfl_xor_sync(0xffffffffu, sqA, 2);
      sB += __shfl_xor_sync(0xffffffffu, sB, 2);  sqB += __shfl_xor_sync(0xffffffffu, sqB, 2);
      float mA = sA*(1.f/32.f), vA = sqA*(1.f/32.f) - mA*mA;
      float mB = sB*(1.f/32.f), vB = sqB*(1.f/32.f) - mB*mB;
      float rA2 = rsqrtf(vA + 1e-5f), rB2 = rsqrtf(vB + 1e-5f);
      float wv = g_wmix[(l*CC + c)*NOPS + o];
      #pragma unroll
      for (int fi=0; fi<4; fi++){
        int f = 4*ch + fi;
        int col0 = wc*64 + f*8 + 2*tig;
        float lg0=s_lg[col0], lg1=s_lg[col0+1], lb0=s_lb[col0], lb1=s_lb[col0+1];
        mix[f][0] += wv*((tv[fi][0]-mA)*rA2*lg0 + lb0);
        mix[f][1] += wv*((tv[fi][1]-mA)*rA2*lg1 + lb1);
        mix[f][2] += wv*((tv[fi][2]-mB)*rB2*lg0 + lb0);
        mix[f][3] += wv*((tv[fi][3]-mB)*rB2*lg1 + lb1);
      }
    }
  }
  int rA = n0 + wr*16 + g;
  int rB = rA + 8;
  #pragma unroll
  for (int f=0; f<8; f++){
    int col = wc*64 + f*8 + 2*tig;
    if (rA < NN) *(float2*)&g_y[(size_t)rA*HH + col] = make_float2(mix[f][0], mix[f][1]);
    if (rB < NN) *(float2*)&g_y[(size_t)rB*HH + col] = make_float2(mix[f][2], mix[f][3]);
  }
}

// ------------------------- BatchNorm stats (fused finisher via last block) -------------------------
__global__ void k_bnstat(const float* __restrict__ bng, const float* __restrict__ bnb, int l){
  int t = threadIdx.x; int b = blockIdx.x;
  float s=0.f, sq=0.f;
  for (int r=b; r<NN; r+=BNG){
    float v = g_y[(size_t)r*HH + t];
    s+=v; sq+=v*v;
  }
  g_part[b*HH+t]=s;
  g_part[BNG*HH + b*HH+t]=sq;
  __threadfence();
  __shared__ int lastS;
  if (t==0) lastS = (atomicAdd(&g_cbn,1) == BNG-1);
  __syncthreads();
  if (lastS){
    float ts=0.f, tq=0.f;
    for (int bb=0;bb<BNG;bb++){ ts+=g_part[bb*HH+t]; tq+=g_part[BNG*HH+bb*HH+t]; }
    float mean = ts*(1.f/NN);
    float var  = tq*(1.f/NN) - mean*mean;
    float sc = bng[l*HH+t]*rsqrtf(var+1e-5f);
    g_scale[t]=sc;
    g_shift[t]=bnb[l*HH+t]-mean*sc;
    if (t==0) g_cbn = 0;
  }
}
__global__ void k_bnapply(int l){
  int i = blockIdx.x*blockDim.x+threadIdx.x;
  if (i < NN*32){
    float4 v = ((const float4*)g_y)[i];
    int cb = (i & 31)*4;
    v.x = v.x*g_scale[cb+0]+g_shift[cb+0];
    v.y = v.y*g_scale[cb+1]+g_shift[cb+1];
    v.z = v.z*g_scale[cb+2]+g_shift[cb+2];
    v.w = v.w*g_scale[cb+3]+g_shift[cb+3];
    ((float4*)(g_gr + (size_t)(l+1)*NN*HH))[i] = v;
  }
}

// ------------------------- virtual node MLP (fused BN stats) -------------------------
__global__ void k_vt(int l){
  int b=blockIdx.x, t=threadIdx.x;
  int s=g_bstart[b], e=g_bstart[b+1];
  float acc=0.f;
  const float* gp = g_gr + (size_t)(l+1)*NN*HH;
  for (int r=s;r<e;r++) acc += gp[(size_t)r*HH+t];
  g_vt[b*HH+t] = acc + g_vn[b*HH+t];
}
// h1 = vt @ W1 + b1 ; last block computes BN1 scale/shift
__global__ void k_vnl1(const float* __restrict__ W1, const float* __restrict__ b1,
                       const float* __restrict__ bn_g, const float* __restrict__ bn_b, int l){
  __shared__ float vr[HH];
  int row=blockIdx.x, t=threadIdx.x;
  if (t<HH) vr[t]=g_vt[row*HH+t];
  __syncthreads();
  float acc = b1[l*2*HH+t];
  const float* w = W1 + (size_t)l*HH*2*HH + t;
  #pragma unroll 4
  for (int h=0;h<HH;h++) acc += vr[h]*w[h*2*HH];
  g_h1[row*2*HH+t]=acc;
  __threadfence();
  __shared__ int lastS;
  if (t==0) lastS = (atomicAdd(&g_c1,1) == NB-1);
  __syncthreads();
  if (lastS){
    float s=0.f, sq=0.f;
    for (int r=0;r<NB;r++){ float v=g_h1[r*2*HH+t]; s+=v; sq+=v*v; }
    float mean=s*(1.f/NB);
    float var=sq*(1.f/NB)-mean*mean;
    float sc = bn_g[l*2*HH+t]*rsqrtf(var+1e-5f);
    g_sc1[t]=sc;
    g_sh1[t]=bn_b[l*2*HH+t]-mean*sc;
    if (t==0) g_c1 = 0;
  }
}
// h2 = relu(bn1(h1)) @ W2 + b2 ; last block computes BN2 scale/shift
__global__ void k_vnl2(const float* __restrict__ W2, const float* __restrict__ b2,
                       const float* __restrict__ bn_g, const float* __restrict__ bn_b, int l){
  __shared__ float hr[2*HH];
  int row=blockIdx.x, t=threadIdx.x;
  {
    float v0 = g_h1[row*2*HH+t]*g_sc1[t]+g_sh1[t];
    float v1 = g_h1[row*2*HH+t+HH]*g_sc1[t+HH]+g_sh1[t+HH];
    hr[t]    = v0>0.f? v0:0.f;
    hr[t+HH] = v1>0.f? v1:0.f;
  }
  __syncthreads();
  float acc = b2[l*HH+t];
  const float* w = W2 + (size_t)l*2*HH*HH + t;
  #pragma unroll 4
  for (int h=0;h<2*HH;h++) acc += hr[h]*w[h*HH];
  g_h2[row*HH+t]=acc;
  __threadfence();
  __shared__ int lastS;
  if (t==0) lastS = (atomicAdd(&g_c2,1) == NB-1);
  __syncthreads();
  if (lastS){
    float s=0.f, sq=0.f;
    for (int r=0;r<NB;r++){ float v=g_h2[r*HH+t]; s+=v; sq+=v*v; }
    float mean=s*(1.f/NB);
    float var=sq*(1.f/NB)-mean*mean;
    float sc = bn_g[l*HH+t]*rsqrtf(var+1e-5f);
    g_sc2[t]=sc;
    g_sh2[t]=bn_b[l*HH+t]-mean*sc;
    if (t==0) g_c2 = 0;
  }
}
__global__ void k_vnapply2(){
  int i = blockIdx.x*blockDim.x+threadIdx.x;
  if (i < NB*HH){
    int t = i & (HH-1);
    float v = g_h2[i]*g_sc2[t]+g_sh2[t];
    g_vn[i] = v>0.f? v:0.f;
  }
}

// ------------------------- pooling + head -------------------------
__global__ void k_pool(){
  int b=blockIdx.x, t=threadIdx.x;
  int s=g_bstart[b], e=g_bstart[b+1];
  float inv = 1.f/(float)max(e-s,1);
  for (int st=0; st<4; st++){
    const float* gp = g_gr + (size_t)st*NN*HH;
    float sum=0.f, mx=-1e30f;
    for (int r=s;r<e;r++){ float v=gp[(size_t)r*HH+t]; sum+=v; mx=fmaxf(mx,v); }
    if (e==s) mx=0.f;
    g_pooled[b*1024 + st*HH + t] = sum*inv;
    g_pooled[b*1024 + 512 + st*HH + t] = mx;
  }
}
__global__ void k_head(const float* __restrict__ hW, const float* __restrict__ hb,
                       const float* __restrict__ hM, float* __restrict__ out){
  __shared__ float red[NOUT];
  int b=blockIdx.x, t=threadIdx.x;
  if (t<NOUT) red[t]=0.f;
  __syncthreads();
  float acc[NOUT];
  #pragma unroll
  for (int j=0;j<NOUT;j++) acc[j]=0.f;
  for (int d=t; d<1024; d+=256){
    float pv = g_pooled[b*1024+d];
    const float* wrow = hW + d*NOUT;
    const float* mrow = hM + d*NOUT;
    #pragma unroll
    for (int j=0;j<NOUT;j++) acc[j] += pv*wrow[j]*mrow[j];
  }
  #pragma unroll
  for (int j=0;j<NOUT;j++) atomicAdd(&red[j], acc[j]);
  __syncthreads();
  if (t<NOUT) out[b*NOUT+t] = red[t] + hb[t];
}

// ------------------------- launch -------------------------
extern "C" void kernel_launch(void* const* d_in, const int* in_sizes, int n_in,
                              void* d_out, int out_size){
  const float* x      = (const float*)d_in[0];
  const int*   ei     = (const int*)d_in[1];
  const int*   batch  = (const int*)d_in[2];
  const float* lin1W  = (const float*)d_in[3];
  const float* lin1b  = (const float*)d_in[4];
  const float* vn0    = (const float*)d_in[5];
  const float* Wops   = (const float*)d_in[6];
  const float* bops   = (const float*)d_in[7];
  const float* atta   = (const float*)d_in[8];
  const float* lng    = (const float*)d_in[9];
  const float* lnb    = (const float*)d_in[10];
  const float* bng    = (const float*)d_in[11];
  const float* bnb    = (const float*)d_in[12];
  const float* vnW1   = (const float*)d_in[13];
  const float* vnb1   = (const float*)d_in[14];
  const float* vnbn1g = (const float*)d_in[15];
  const float* vnbn1b = (const float*)d_in[16];
  const float* vnW2   = (const float*)d_in[17];
  const float* vnb2   = (const float*)d_in[18];
  const float* vnbn2g = (const float*)d_in[19];
  const float* vnbn2b = (const float*)d_in[20];
  const float* alphas = (const float*)d_in[21];
  const float* headW  = (const float*)d_in[22];
  const float* headb  = (const float*)d_in[23];
  const float* headM  = (const float*)d_in[24];
  float* out = (float*)d_out;
  const int* src = ei;
  const int* dst = ei + NE;

  cudaFuncSetAttribute(k_mix_mma, cudaFuncAttributeMaxDynamicSharedMemorySize, SMEM_MIX);
  cudaFuncSetAttribute(k_lin1_mma, cudaFuncAttributeMaxDynamicSharedMemorySize, SMEM_L1);

  const int NBLK = (NN + 255)/256;
  const int WBLK = (NN*32 + 255)/256;
  const int EBLK = (NE + 255)/256;
  const int MIXBLK = (NN + MT-1)/MT;   // 782

  k_zero_deg<<<NBLK,256>>>();
  k_count<<<EBLK,256>>>(dst);
  k_scan<<<1,1024>>>();
  k_wprep1<<<(128*64+255)/256,256>>>(lin1W);
  k_wprep<<<(LL*NOPS*16384+255)/256,256>>>(Wops);
  k_lin1_mma<<<MIXBLK,256,SMEM_L1>>>(x, lin1b);
  k_scatter<<<EBLK,256>>>(src, dst);
  k_bstart<<<NBLK,256>>>(batch);
  k_prepw<<<1,32>>>(alphas);
  k_vninit<<<(NB*HH+255)/256,256>>>(vn0);

  for (int l=0; l<LL; l++){
    k_nodeA<<<WBLK,256>>>(batch, atta, l);
    k_edge<<<WBLK,256>>>();
    k_mix_mma<<<MIXBLK,256,SMEM_MIX>>>(l, bops, lng, lnb);
    k_bnstat<<<BNG,128>>>(bng, bnb, l);
    k_bnapply<<<(NN*32+255)/256,256>>>(l);
    if (l < LL-1){
      k_vt<<<NB,128>>>(l);
      k_vnl1<<<NB,256>>>(vnW1, vnb1, vnbn1g, vnbn1b, l);
      k_vnl2<<<NB,128>>>(vnW2, vnb2, vnbn2g, vnbn2b, l);
      k_vnapply2<<<(NB*HH+255)/256,256>>>();
    }
  }
  k_pool<<<NB,128>>>();
  k_head<<<NB,256>>>(headW, headb, headM, out);
}